// round 3
// baseline (speedup 1.0000x reference)
#include <cuda_runtime.h>
#include <math.h>

// ---------------- problem constants ----------------
#define T_LEN 131072
#define NB 16            // batch
#define NCHA 2           // audio channels
#define NSEQ (NB*NCHA)   // 32 filter sequences
#define NBAND 3
#define NBS (NBAND*NB)   // 48 band-smoother sequences
#define SRATE 44100.0f

// biquad blocked-scan config
#define BQ_NT 1024
#define BQ_C (T_LEN/BQ_NT)    // 128 samples per thread
#define BQ_LEV 10             // log2(BQ_NT)

// smoothing chunk config
#define SM_CHUNK 4096
#define SM_NCH (T_LEN/SM_CHUNK)   // 32 chunks
#define SM_WARM 24576             // warmup samples (contraction e^-12.3)

// ---------------- scratch (static device arrays; no allocation) ----------------
__device__ float g_xd [NSEQ*T_LEN];   // distorted input
__device__ float g_t1 [NSEQ*T_LEN];   // low biquad pass 1
__device__ float g_t2 [NSEQ*T_LEN];   // high biquad pass 1
__device__ float g_low[NSEQ*T_LEN];
__device__ float g_high[NSEQ*T_LEN];
__device__ float g_gin[NBS*T_LEN];    // instantaneous band gains
__device__ float g_gsm[NBS*T_LEN];    // smoothed band gains
__device__ float g_xm [NSEQ*T_LEN];   // multiband-mixed signal
__device__ float g_det[NB*T_LEN];     // limiter detector
__device__ float g_lg [NB*T_LEN];     // limiter gain

struct BQ  { float na1, na2, b0, k1, k2; };     // DF2T: z1'=na1*z1+z2+k1*x ; z2'=na2*z1+k2*x ; y=b0*x+z1
struct BSM { float at, rt, ct, sc, et, se; int useMin; };
struct LSM { float at, rt, lt; int useMin; };

__device__ BQ  d_bq[2*NB];     // [0..15] low, [16..31] high
__device__ BSM d_bsm[NBS];     // band-major: seq = band*16 + b
__device__ LSM d_lsm[NB];
__device__ float d_w[NB], d_gd[NB], d_mb[NB];

// ---------------- setup ----------------
__global__ void k_setup(const float* __restrict__ drive, const float* __restrict__ dmix,
                        const float* __restrict__ locut, const float* __restrict__ hicut,
                        const float* __restrict__ mbmix,
                        const float* __restrict__ ct, const float* __restrict__ cr,
                        const float* __restrict__ et, const float* __restrict__ er,
                        const float* __restrict__ atms, const float* __restrict__ rtms,
                        const float* __restrict__ lth, const float* __restrict__ lat,
                        const float* __restrict__ lrt)
{
    int i = threadIdx.x;
    if (i < NB) {
        d_w[i]  = dmix[i];
        d_gd[i] = exp2f(drive[i] * 0.16609640474436813f);   // 10^(db/20)
        d_mb[i] = mbmix[i];
        for (int f = 0; f < 2; ++f) {
            double cut = (f == 0) ? (double)locut[i] : (double)hicut[i];
            double w0 = 2.0 * 3.14159265358979323846 * cut / 44100.0;
            double al = sin(w0) * 0.70710678118654752;
            double c  = cos(w0);
            double b0, b1, b2;
            if (f == 0) { b0 = (1.0 - c) * 0.5; b1 = 1.0 - c;    b2 = (1.0 - c) * 0.5; }
            else        { b0 = (1.0 + c) * 0.5; b1 = -(1.0 + c); b2 = (1.0 + c) * 0.5; }
            double a0 = 1.0 + al;
            b0 /= a0; b1 /= a0; b2 /= a0;
            double a1 = -2.0 * c / a0, a2 = (1.0 - al) / a0;
            BQ q;
            q.na1 = (float)(-a1); q.na2 = (float)(-a2); q.b0 = (float)b0;
            q.k1  = (float)(b1 - a1 * b0);
            q.k2  = (float)(b2 - a2 * b0);
            d_bq[f*NB + i] = q;
        }
        float at = 1.f - expf(-2200.f / (lat[i] * SRATE));
        float rt = 1.f - expf(-2200.f / (lrt[i] * SRATE));
        LSM l; l.at = at; l.rt = rt;
        l.lt = exp2f(lth[i] * 0.16609640474436813f);
        l.useMin = (at < rt);   // attack_on_rise=True
        d_lsm[i] = l;
    }
    if (i < NBS) {
        int band = i / NB, b = i % NB;
        int idx = b*3 + band;
        float at = 1.f - expf(-2200.f / (atms[idx] * SRATE));
        float rt = 1.f - expf(-2200.f / (rtms[idx] * SRATE));
        BSM s;
        s.at = at; s.rt = rt; s.useMin = (at >= rt);   // attack_on_rise=False
        s.ct = ct[idx]; s.sc = 1.f - 1.f / cr[idx];
        s.et = et[idx]; s.se = 1.f - 1.f / er[idx];
        d_bsm[i] = s;
    }
}

// ---------------- distortion ----------------
__global__ void k_dist(const float* __restrict__ x)
{
    int idx = blockIdx.x * blockDim.x + threadIdx.x;
    const int n4 = NSEQ * T_LEN / 4;
    if (idx >= n4) return;
    int b = idx >> 16;                  // (NCHA*T_LEN/4) = 65536 float4 per batch
    float w = d_w[b], gd = d_gd[b], ow = 1.f - w;
    float4 v = __ldg(((const float4*)x) + idx);
    v.x = fmaf(w, tanhf(v.x * gd), ow * v.x);
    v.y = fmaf(w, tanhf(v.y * gd), ow * v.y);
    v.z = fmaf(w, tanhf(v.z * gd), ow * v.z);
    v.w = fmaf(w, tanhf(v.w * gd), ow * v.w);
    ((float4*)g_xd)[idx] = v;
}

// ---------------- biquad (blocked state-space scan, exact) ----------------
__device__ __forceinline__ void bqstep(float x, float& z1, float& z2, const BQ& c)
{
    float t  = fmaf(c.k1, x, z2);
    float n2 = fmaf(c.na2, z1, c.k2 * x);
    z1 = fmaf(c.na1, z1, t);
    z2 = n2;
}
__device__ __forceinline__ float bqstep_y(float x, float& z1, float& z2, const BQ& c)
{
    float y  = fmaf(c.b0, x, z1);
    float t  = fmaf(c.k1, x, z2);
    float n2 = fmaf(c.na2, z1, c.k2 * x);
    z1 = fmaf(c.na1, z1, t);
    z2 = n2;
    return y;
}

__global__ void k_biquad(int pass)
{
    __shared__ float2 sF[BQ_NT];
    __shared__ float  sP[BQ_LEV][4];
    int blk = blockIdx.x;
    int f = blk >> 5;          // 0 = low chain, 1 = high chain
    int s = blk & 31;          // sequence (b*2 + ch)
    int b = s >> 1;
    const float* in; float* out;
    if (pass == 0) { in = g_xd;              out = f ? g_t2  : g_t1; }
    else           { in = f ? g_t2 : g_t1;   out = f ? g_high : g_low; }
    BQ cf = d_bq[f*NB + b];
    int tid = threadIdx.x;

    if (tid == 0) {
        // A = [[na1, 1],[na2, 0]]; compute A^128 then its squarings, in double
        double m00 = (double)cf.na1, m01 = 1.0, m10 = (double)cf.na2, m11 = 0.0;
        for (int k = 0; k < 7; ++k) {
            double t00 = m00*m00 + m01*m10, t01 = m00*m01 + m01*m11;
            double t10 = m10*m00 + m11*m10, t11 = m10*m01 + m11*m11;
            m00 = t00; m01 = t01; m10 = t10; m11 = t11;
        }
        for (int lv = 0; lv < BQ_LEV; ++lv) {
            sP[lv][0] = (float)m00; sP[lv][1] = (float)m01;
            sP[lv][2] = (float)m10; sP[lv][3] = (float)m11;
            double t00 = m00*m00 + m01*m10, t01 = m00*m01 + m01*m11;
            double t10 = m10*m00 + m11*m10, t11 = m10*m01 + m11*m11;
            m00 = t00; m01 = t01; m10 = t10; m11 = t11;
        }
    }

    const float4* in4 = (const float4*)(in + (size_t)s * T_LEN + (size_t)tid * BQ_C);

    // phase A: zero-state run, keep only final state
    float z1 = 0.f, z2 = 0.f;
#pragma unroll 8
    for (int i = 0; i < BQ_C/4; ++i) {
        float4 v = __ldg(in4 + i);
        bqstep(v.x, z1, z2, cf);
        bqstep(v.y, z1, z2, cf);
        bqstep(v.z, z1, z2, cf);
        bqstep(v.w, z1, z2, cf);
    }
    __syncthreads();   // sP visible + sF safe

    // Kogge-Stone scan: F_j = sum_{i<=j} (A^C)^(j-i) s_i
    float2 my = make_float2(z1, z2);
#pragma unroll
    for (int lv = 0; lv < BQ_LEV; ++lv) {
        sF[tid] = my;
        __syncthreads();
        int d = 1 << lv;
        if (tid >= d) {
            float2 o = sF[tid - d];
            float p00 = sP[lv][0], p01 = sP[lv][1], p10 = sP[lv][2], p11 = sP[lv][3];
            my.x += p00 * o.x + p01 * o.y;
            my.y += p10 * o.x + p11 * o.y;
        }
        __syncthreads();
    }
    sF[tid] = my;
    __syncthreads();
    float2 e = (tid > 0) ? sF[tid - 1] : make_float2(0.f, 0.f);

    // phase B: re-run with correct incoming state, emit outputs
    z1 = e.x; z2 = e.y;
    float4* out4 = (float4*)(out + (size_t)s * T_LEN + (size_t)tid * BQ_C);
#pragma unroll 8
    for (int i = 0; i < BQ_C/4; ++i) {
        float4 v = __ldg(in4 + i);
        float4 r;
        r.x = bqstep_y(v.x, z1, z2, cf);
        r.y = bqstep_y(v.y, z1, z2, cf);
        r.z = bqstep_y(v.z, z1, z2, cf);
        r.w = bqstep_y(v.w, z1, z2, cf);
        out4[i] = r;
    }
}

// ---------------- instantaneous band gain ----------------
__device__ __forceinline__ float comp_gain(float det, const BSM& p)
{
    float xdb = 6.0205999132796239f * log2f(fmaxf(det, 1e-7f));   // 20*log10
    float gdb = fminf(fminf(p.sc * (p.ct - xdb), p.se * (p.et - xdb)), 0.f);
    return exp2f(gdb * 0.16609640474436813f);                      // 10^(gdb/20)
}

__global__ void k_bandgain()
{
    int idx = blockIdx.x * blockDim.x + threadIdx.x;
    const int per = T_LEN / 4;
    if (idx >= NB * per) return;
    int b = idx / per, t4 = idx - b * per;
    size_t o0 = (size_t)b * (NCHA*T_LEN) + ((size_t)t4 << 2);
    float4 x0 = *(const float4*)(g_xd  + o0);
    float4 x1 = *(const float4*)(g_xd  + o0 + T_LEN);
    float4 l0 = *(const float4*)(g_low + o0);
    float4 l1 = *(const float4*)(g_low + o0 + T_LEN);
    float4 h0 = *(const float4*)(g_high + o0);
    float4 h1 = *(const float4*)(g_high + o0 + T_LEN);
    BSM pl = d_bsm[0*NB + b], pm = d_bsm[1*NB + b], ph = d_bsm[2*NB + b];
    float4 gl, gm, gh;
#define GLANE(L) { \
    float ls = l0.L + l1.L, hs = h0.L + h1.L, xs = x0.L + x1.L; \
    gl.L = comp_gain(fabsf(ls), pl); \
    gm.L = comp_gain(fabsf(xs - ls - hs), pm); \
    gh.L = comp_gain(fabsf(hs), ph); }
    GLANE(x) GLANE(y) GLANE(z) GLANE(w)
#undef GLANE
    size_t gb = (size_t)t4 << 2;
    *(float4*)(g_gin + (size_t)(0*NB + b) * T_LEN + gb) = gl;
    *(float4*)(g_gin + (size_t)(1*NB + b) * T_LEN + gb) = gm;
    *(float4*)(g_gin + (size_t)(2*NB + b) * T_LEN + gb) = gh;
}

// ---------------- nonlinear smoothing (chunked + warmup, contraction-safe) ----------------
template<bool USEMIN>
__device__ __forceinline__ float smstep(float f, float g, float at, float rt)
{
    float d = g - f;
    float u = fmaf(at, d, f);
    float v = fmaf(rt, d, f);
    return USEMIN ? fminf(u, v) : fmaxf(u, v);
}

template<bool USEMIN, bool LIM>
__device__ void smooth_chunk(const float* __restrict__ src, float* __restrict__ dst,
                             float at, float rt, float lt,
                             float f, int wstart, int start, int end)
{
    const int nit = (end - wstart) >> 2;       // always a multiple of 8 here
    const float4* s4 = (const float4*)(src + wstart);
    float4 buf[8];
#pragma unroll
    for (int j = 0; j < 8; ++j) buf[j] = (j < nit) ? __ldg(s4 + j) : make_float4(0.f,0.f,0.f,0.f);
    int t = wstart;
    for (int base = 0; base < nit; base += 8) {
#pragma unroll
        for (int j = 0; j < 8; ++j) {
            float4 v = buf[j];
            int nxt = base + 8 + j;
            if (nxt < nit) buf[j] = __ldg(s4 + nxt);
            float4 r;
            f = smstep<USEMIN>(f, v.x, at, rt); r.x = f;
            f = smstep<USEMIN>(f, v.y, at, rt); r.y = f;
            f = smstep<USEMIN>(f, v.z, at, rt); r.z = f;
            f = smstep<USEMIN>(f, v.w, at, rt); r.w = f;
            if (LIM) {
                r.x = fminf(1.f, lt / fmaxf(r.x, 1e-7f));
                r.y = fminf(1.f, lt / fmaxf(r.y, 1e-7f));
                r.z = fminf(1.f, lt / fmaxf(r.z, 1e-7f));
                r.w = fminf(1.f, lt / fmaxf(r.w, 1e-7f));
            }
            if (t >= start) *(float4*)(dst + t) = r;
            t += 4;
        }
    }
}

__global__ void k_smooth_band()
{
    int tid = blockIdx.x * blockDim.x + threadIdx.x;
    if (tid >= NBS * SM_NCH) return;
    int seq = tid >> 5;          // SM_NCH == 32 -> warp-uniform sequence
    int c   = tid & 31;
    BSM p = d_bsm[seq];
    const float* src = g_gin + (size_t)seq * T_LEN;
    float*       dst = g_gsm + (size_t)seq * T_LEN;
    int start = c * SM_CHUNK, end = start + SM_CHUNK;
    int wstart = start - SM_WARM; if (wstart < 0) wstart = 0;
    float f = (wstart == 0) ? 1.0f : __ldg(src + wstart);
    if (p.useMin) smooth_chunk<true, false>(src, dst, p.at, p.rt, 0.f, f, wstart, start, end);
    else          smooth_chunk<false,false>(src, dst, p.at, p.rt, 0.f, f, wstart, start, end);
}

__global__ void k_smooth_lim()
{
    int tid = blockIdx.x * blockDim.x + threadIdx.x;
    if (tid >= NB * SM_NCH) return;
    int b = tid >> 5;
    int c = tid & 31;
    LSM p = d_lsm[b];
    const float* src = g_det + (size_t)b * T_LEN;
    float*       dst = g_lg  + (size_t)b * T_LEN;
    int start = c * SM_CHUNK, end = start + SM_CHUNK;
    int wstart = start - SM_WARM; if (wstart < 0) wstart = 0;
    float f = (wstart == 0) ? 0.0f : __ldg(src + wstart);
    if (p.useMin) smooth_chunk<true, true>(src, dst, p.at, p.rt, p.lt, f, wstart, start, end);
    else          smooth_chunk<false,true>(src, dst, p.at, p.rt, p.lt, f, wstart, start, end);
}

// ---------------- band mix + limiter detector ----------------
__global__ void k_mix()
{
    int idx = blockIdx.x * blockDim.x + threadIdx.x;
    const int per = T_LEN / 4;
    if (idx >= NB * per) return;
    int b = idx / per, t4 = idx - b * per;
    size_t o0 = (size_t)b * (NCHA*T_LEN) + ((size_t)t4 << 2);
    size_t gb = (size_t)t4 << 2;
    float4 x0 = *(const float4*)(g_xd  + o0);
    float4 x1 = *(const float4*)(g_xd  + o0 + T_LEN);
    float4 l0 = *(const float4*)(g_low + o0);
    float4 l1 = *(const float4*)(g_low + o0 + T_LEN);
    float4 h0 = *(const float4*)(g_high + o0);
    float4 h1 = *(const float4*)(g_high + o0 + T_LEN);
    float4 gl = *(const float4*)(g_gsm + (size_t)(0*NB + b) * T_LEN + gb);
    float4 gm = *(const float4*)(g_gsm + (size_t)(1*NB + b) * T_LEN + gb);
    float4 gh = *(const float4*)(g_gsm + (size_t)(2*NB + b) * T_LEN + gb);
    float mb = d_mb[b], om = 1.f - mb;
    float4 m0, m1, dt;
#define MLANE(L) { \
    float mid0 = x0.L - l0.L - h0.L; \
    float y0 = l0.L*gl.L + mid0*gm.L + h0.L*gh.L; \
    float a0 = mb*y0 + om*x0.L; \
    float mid1 = x1.L - l1.L - h1.L; \
    float y1 = l1.L*gl.L + mid1*gm.L + h1.L*gh.L; \
    float a1 = mb*y1 + om*x1.L; \
    m0.L = a0; m1.L = a1; dt.L = fabsf(a0 + a1); }
    MLANE(x) MLANE(y) MLANE(z) MLANE(w)
#undef MLANE
    *(float4*)(g_xm + o0)         = m0;
    *(float4*)(g_xm + o0 + T_LEN) = m1;
    *(float4*)(g_det + (size_t)b * T_LEN + gb) = dt;
}

// ---------------- final limiter application ----------------
__global__ void k_final(float* __restrict__ out)
{
    int idx = blockIdx.x * blockDim.x + threadIdx.x;
    const int per = T_LEN / 4;
    if (idx >= NB * per) return;
    int b = idx / per, t4 = idx - b * per;
    size_t o0 = (size_t)b * (NCHA*T_LEN) + ((size_t)t4 << 2);
    float4 lg = *(const float4*)(g_lg + (size_t)b * T_LEN + ((size_t)t4 << 2));
    float4 m0 = *(const float4*)(g_xm + o0);
    float4 m1 = *(const float4*)(g_xm + o0 + T_LEN);
    m0.x *= lg.x; m0.y *= lg.y; m0.z *= lg.z; m0.w *= lg.w;
    m1.x *= lg.x; m1.y *= lg.y; m1.z *= lg.z; m1.w *= lg.w;
    *(float4*)(out + o0)         = m0;
    *(float4*)(out + o0 + T_LEN) = m1;
}

// ---------------- launcher ----------------
extern "C" void kernel_launch(void* const* d_in, const int* in_sizes, int n_in,
                              void* d_out, int out_size)
{
    const float* x     = (const float*)d_in[0];
    const float* drive = (const float*)d_in[1];
    const float* dmix  = (const float*)d_in[2];
    const float* locut = (const float*)d_in[3];
    const float* hicut = (const float*)d_in[4];
    const float* mbmix = (const float*)d_in[5];
    const float* ct    = (const float*)d_in[6];
    const float* cr    = (const float*)d_in[7];
    const float* et    = (const float*)d_in[8];
    const float* er    = (const float*)d_in[9];
    const float* atms  = (const float*)d_in[10];
    const float* rtms  = (const float*)d_in[11];
    const float* lth   = (const float*)d_in[12];
    const float* lat   = (const float*)d_in[13];
    const float* lrt   = (const float*)d_in[14];
    (void)in_sizes; (void)n_in; (void)out_size;

    k_setup<<<1, 64>>>(drive, dmix, locut, hicut, mbmix, ct, cr, et, er,
                       atms, rtms, lth, lat, lrt);
    k_dist<<<(NSEQ*T_LEN/4 + 255)/256, 256>>>(x);
    k_biquad<<<64, BQ_NT>>>(0);
    k_biquad<<<64, BQ_NT>>>(1);
    k_bandgain<<<(NB*T_LEN/4 + 255)/256, 256>>>();
    k_smooth_band<<<(NBS*SM_NCH + 127)/128, 128>>>();
    k_mix<<<(NB*T_LEN/4 + 255)/256, 256>>>();
    k_smooth_lim<<<(NB*SM_NCH + 127)/128, 128>>>();
    k_final<<<(NB*T_LEN/4 + 255)/256, 256>>>((float*)d_out);
}

// round 5
// speedup vs baseline: 3.3781x; 3.3781x over previous
#include <cuda_runtime.h>
#include <math.h>

// ---------------- problem constants ----------------
#define T_LEN 131072
#define NB 16
#define NCHA 2
#define NSEQ (NB*NCHA)
#define NBAND 3
#define NBS (NBAND*NB)
#define SRATE 44100.0f

// biquad config: 256 threads x 512-sample chunks
#define BQ_NT 256
#define BQ_C 512
#define BQ_LEV 8

// smoother config: 32 chunks of 4096, 16384-sample warmup (4 chunks)
#define SM_CH 4096

// ---------------- scratch ----------------
__device__ float g_xd  [NSEQ*T_LEN];   // distorted input (natural layout)
__device__ float g_t1  [NSEQ*T_LEN];   // low biquad stage1 (B layout: (t%512)*256 + t/512)
__device__ float g_t2  [NSEQ*T_LEN];   // high biquad stage1 (B layout)
__device__ float g_low [NSEQ*T_LEN];   // natural
__device__ float g_high[NSEQ*T_LEN];   // natural
__device__ float g_gin [NBS*T_LEN];    // L2 layout: (t%4096)*32 + t/4096
__device__ float g_gsm [NBS*T_LEN];    // L2 layout
__device__ float g_xm  [NSEQ*T_LEN];   // natural
__device__ float g_det [NB*T_LEN];     // L2 layout
__device__ float g_lg  [NB*T_LEN];     // L2 layout

struct BQ  { float na1, na2, b0, k1, k2; };
struct BSM { float at, rt, ct, sc, et, se; int useMin; };
struct LSM { float at, rt, lt; int useMin; };

__device__ BQ  d_bq[2*NB];
__device__ BSM d_bsm[NBS];      // band-major: seq = band*16 + b
__device__ LSM d_lsm[NB];
__device__ float d_w[NB], d_gd[NB], d_mb[NB];

// ---------------- setup ----------------
__global__ void k_setup(const float* __restrict__ drive, const float* __restrict__ dmix,
                        const float* __restrict__ locut, const float* __restrict__ hicut,
                        const float* __restrict__ mbmix,
                        const float* __restrict__ ct, const float* __restrict__ cr,
                        const float* __restrict__ et, const float* __restrict__ er,
                        const float* __restrict__ atms, const float* __restrict__ rtms,
                        const float* __restrict__ lth, const float* __restrict__ lat,
                        const float* __restrict__ lrt)
{
    int i = threadIdx.x;
    if (i < NB) {
        d_w[i]  = dmix[i];
        d_gd[i] = exp2f(drive[i] * 0.16609640474436813f);
        d_mb[i] = mbmix[i];
        for (int f = 0; f < 2; ++f) {
            double cut = (f == 0) ? (double)locut[i] : (double)hicut[i];
            double w0 = 2.0 * 3.14159265358979323846 * cut / 44100.0;
            double al = sin(w0) * 0.70710678118654752;
            double c  = cos(w0);
            double b0, b1, b2;
            if (f == 0) { b0 = (1.0 - c) * 0.5; b1 = 1.0 - c;    b2 = (1.0 - c) * 0.5; }
            else        { b0 = (1.0 + c) * 0.5; b1 = -(1.0 + c); b2 = (1.0 + c) * 0.5; }
            double a0 = 1.0 + al;
            b0 /= a0; b1 /= a0; b2 /= a0;
            double a1 = -2.0 * c / a0, a2 = (1.0 - al) / a0;
            BQ q;
            q.na1 = (float)(-a1); q.na2 = (float)(-a2); q.b0 = (float)b0;
            q.k1  = (float)(b1 - a1 * b0);
            q.k2  = (float)(b2 - a2 * b0);
            d_bq[f*NB + i] = q;
        }
        float at = 1.f - expf(-2200.f / (lat[i] * SRATE));
        float rt = 1.f - expf(-2200.f / (lrt[i] * SRATE));
        LSM l; l.at = at; l.rt = rt;
        l.lt = exp2f(lth[i] * 0.16609640474436813f);
        l.useMin = (at < rt);
        d_lsm[i] = l;
    }
    if (i < NBS) {
        int band = i / NB, b = i % NB;
        int idx = b*3 + band;
        float at = 1.f - expf(-2200.f / (atms[idx] * SRATE));
        float rt = 1.f - expf(-2200.f / (rtms[idx] * SRATE));
        BSM s;
        s.at = at; s.rt = rt; s.useMin = (at >= rt);
        s.ct = ct[idx]; s.sc = 1.f - 1.f / cr[idx];
        s.et = et[idx]; s.se = 1.f - 1.f / er[idx];
        d_bsm[i] = s;
    }
}

// ---------------- distortion ----------------
__global__ void k_dist(const float* __restrict__ x)
{
    int idx = blockIdx.x * blockDim.x + threadIdx.x;
    const int n4 = NSEQ * T_LEN / 4;
    if (idx >= n4) return;
    int b = idx >> 16;
    float w = d_w[b], gd = d_gd[b], ow = 1.f - w;
    float4 v = __ldg(((const float4*)x) + idx);
#define TLANE(L) { \
    float z = fminf(fmaxf(v.L * gd, -40.f), 40.f); \
    float e = __expf(2.f * z); \
    float th = __fdividef(e - 1.f, e + 1.f); \
    v.L = fmaf(w, th, ow * v.L); }
    TLANE(x) TLANE(y) TLANE(z) TLANE(w)
#undef TLANE
    ((float4*)g_xd)[idx] = v;
}

// ---------------- biquad core ----------------
__device__ __forceinline__ void bqstep(float x, float& z1, float& z2, const BQ& c)
{
    float t  = fmaf(c.k1, x, z2);
    float n2 = fmaf(c.na2, z1, c.k2 * x);
    z1 = fmaf(c.na1, z1, t);
    z2 = n2;
}
__device__ __forceinline__ float bqstep_y(float x, float& z1, float& z2, const BQ& c)
{
    float y  = fmaf(c.b0, x, z1);
    float t  = fmaf(c.k1, x, z2);
    float n2 = fmaf(c.na2, z1, c.k2 * x);
    z1 = fmaf(c.na1, z1, t);
    z2 = n2;
    return y;
}

__device__ __forceinline__ void bq_make_sP(const BQ& cf, float sP[BQ_LEV][4])
{
    // A = [[na1,1],[na2,0]] ; A^512 then successive squarings
    double m00 = (double)cf.na1, m01 = 1.0, m10 = (double)cf.na2, m11 = 0.0;
    for (int k = 0; k < 9; ++k) {
        double t00 = m00*m00 + m01*m10, t01 = m00*m01 + m01*m11;
        double t10 = m10*m00 + m11*m10, t11 = m10*m01 + m11*m11;
        m00 = t00; m01 = t01; m10 = t10; m11 = t11;
    }
    for (int lv = 0; lv < BQ_LEV; ++lv) {
        sP[lv][0] = (float)m00; sP[lv][1] = (float)m01;
        sP[lv][2] = (float)m10; sP[lv][3] = (float)m11;
        double t00 = m00*m00 + m01*m10, t01 = m00*m01 + m01*m11;
        double t10 = m10*m00 + m11*m10, t11 = m10*m01 + m11*m11;
        m00 = t00; m01 = t01; m10 = t10; m11 = t11;
    }
}

// pass 0: reads g_xd (natural) via smem transpose tiles, writes t1/t2 in B layout
__global__ void k_bq_pass0()
{
    __shared__ float  sT[8][32][33];
    __shared__ float2 sF[BQ_NT];
    __shared__ float  sP[BQ_LEV][4];
    int blk = blockIdx.x;
    int f = blk >> 5, s = blk & 31, b = s >> 1;
    const float* in = g_xd + (size_t)s * T_LEN;
    float* out = (f ? g_t2 : g_t1) + (size_t)s * T_LEN;
    BQ cf = d_bq[f*NB + b];
    int tid = threadIdx.x, w = tid >> 5, l = tid & 31;

    if (tid == 0) bq_make_sP(cf, sP);

    const float* wbase = in + (size_t)(w*32) * BQ_C;   // rows r: +r*512

    float nv[32];
#pragma unroll
    for (int r = 0; r < 32; ++r) nv[r] = __ldg(wbase + r*BQ_C + l);

    // phase A: state only
    float z1 = 0.f, z2 = 0.f;
    for (int tile = 0; tile < 16; ++tile) {
        __syncwarp();
#pragma unroll
        for (int r = 0; r < 32; ++r) sT[w][r][l] = nv[r];
        __syncwarp();
        if (tile < 15) {
#pragma unroll
            for (int r = 0; r < 32; ++r) nv[r] = __ldg(wbase + r*BQ_C + (tile+1)*32 + l);
        }
#pragma unroll
        for (int i = 0; i < 32; ++i) { float xv = sT[w][l][i]; bqstep(xv, z1, z2, cf); }
    }
    __syncthreads();

    // Kogge-Stone scan over 256 chunk states
    float2 my = make_float2(z1, z2);
#pragma unroll
    for (int lv = 0; lv < BQ_LEV; ++lv) {
        sF[tid] = my;
        __syncthreads();
        int d = 1 << lv;
        if (tid >= d) {
            float2 o = sF[tid - d];
            my.x += sP[lv][0]*o.x + sP[lv][1]*o.y;
            my.y += sP[lv][2]*o.x + sP[lv][3]*o.y;
        }
        __syncthreads();
    }
    sF[tid] = my;
    __syncthreads();
    float2 e = (tid > 0) ? sF[tid-1] : make_float2(0.f, 0.f);

    // phase B: regenerate with true state, emit B-layout (coalesced)
    z1 = e.x; z2 = e.y;
#pragma unroll
    for (int r = 0; r < 32; ++r) nv[r] = __ldg(wbase + r*BQ_C + l);
    for (int tile = 0; tile < 16; ++tile) {
        __syncwarp();
#pragma unroll
        for (int r = 0; r < 32; ++r) sT[w][r][l] = nv[r];
        __syncwarp();
        if (tile < 15) {
#pragma unroll
            for (int r = 0; r < 32; ++r) nv[r] = __ldg(wbase + r*BQ_C + (tile+1)*32 + l);
        }
#pragma unroll
        for (int i = 0; i < 32; ++i) {
            float xv = sT[w][l][i];
            float y = bqstep_y(xv, z1, z2, cf);
            out[(size_t)(tile*32 + i)*BQ_NT + tid] = y;
        }
    }
}

// pass 1: reads t1/t2 (B layout, coalesced + register ring), writes low/high natural via smem tiles
__global__ void k_bq_pass1()
{
    __shared__ float  sO[8][32][33];
    __shared__ float2 sF[BQ_NT];
    __shared__ float  sP[BQ_LEV][4];
    int blk = blockIdx.x;
    int f = blk >> 5, s = blk & 31, b = s >> 1;
    const float* in = (f ? g_t2 : g_t1) + (size_t)s * T_LEN;
    float* out = (f ? g_high : g_low) + (size_t)s * T_LEN;
    BQ cf = d_bq[f*NB + b];
    int tid = threadIdx.x, w = tid >> 5, l = tid & 31;

    if (tid == 0) bq_make_sP(cf, sP);

    // phase A
    float ring[32];
#pragma unroll
    for (int j = 0; j < 32; ++j) ring[j] = __ldg(in + j*BQ_NT + tid);
    float z1 = 0.f, z2 = 0.f;
    for (int base = 0; base < BQ_C; base += 32) {
#pragma unroll
        for (int j = 0; j < 32; ++j) {
            float xv = ring[j];
            int nx = base + 32 + j;
            if (nx < BQ_C) ring[j] = __ldg(in + nx*BQ_NT + tid);
            bqstep(xv, z1, z2, cf);
        }
    }
    __syncthreads();

    float2 my = make_float2(z1, z2);
#pragma unroll
    for (int lv = 0; lv < BQ_LEV; ++lv) {
        sF[tid] = my;
        __syncthreads();
        int d = 1 << lv;
        if (tid >= d) {
            float2 o = sF[tid - d];
            my.x += sP[lv][0]*o.x + sP[lv][1]*o.y;
            my.y += sP[lv][2]*o.x + sP[lv][3]*o.y;
        }
        __syncthreads();
    }
    sF[tid] = my;
    __syncthreads();
    float2 e = (tid > 0) ? sF[tid-1] : make_float2(0.f, 0.f);

    // phase B
    z1 = e.x; z2 = e.y;
#pragma unroll
    for (int j = 0; j < 32; ++j) ring[j] = __ldg(in + j*BQ_NT + tid);
    float* wout = out + (size_t)(w*32) * BQ_C;
    for (int tile = 0; tile < 16; ++tile) {
#pragma unroll
        for (int j = 0; j < 32; ++j) {
            float xv = ring[j];
            int nx = tile*32 + 32 + j;
            if (nx < BQ_C) ring[j] = __ldg(in + nx*BQ_NT + tid);
            float y = bqstep_y(xv, z1, z2, cf);
            sO[w][l][j] = y;
        }
        __syncwarp();
#pragma unroll
        for (int r = 0; r < 32; ++r) wout[r*BQ_C + tile*32 + l] = sO[w][r][l];
        __syncwarp();
    }
}

// ---------------- instantaneous band gain (natural reads -> L2-layout writes) ----------------
__device__ __forceinline__ float comp_gain(float det, const BSM& p)
{
    float xdb = 6.0205999132796239f * __log2f(fmaxf(det, 1e-7f));
    float gdb = fminf(fminf(p.sc * (p.ct - xdb), p.se * (p.et - xdb)), 0.f);
    return exp2f(gdb * 0.16609640474436813f);
}

__global__ void k_bandgain()
{
    __shared__ float tl[3][32][33];
    int i0 = blockIdx.x * 32;
    int b  = blockIdx.y;
    int tx = threadIdx.x, ty = threadIdx.y;
    int t = ty*SM_CH + i0 + tx;
    size_t base = (size_t)b * (NCHA*T_LEN) + t;
    float x0 = g_xd [base], x1 = g_xd [base + T_LEN];
    float l0 = g_low[base], l1 = g_low[base + T_LEN];
    float h0 = g_high[base], h1 = g_high[base + T_LEN];
    float ls = l0 + l1, hs = h0 + h1, xs = x0 + x1;
    BSM pl = d_bsm[0*NB + b], pm = d_bsm[1*NB + b], ph = d_bsm[2*NB + b];
    tl[0][ty][tx] = comp_gain(fabsf(ls), pl);
    tl[1][ty][tx] = comp_gain(fabsf(xs - ls - hs), pm);
    tl[2][ty][tx] = comp_gain(fabsf(hs), ph);
    __syncthreads();
    size_t go = (size_t)(i0 + ty)*32 + tx;   // L2 layout
    g_gin[(size_t)(0*NB + b)*T_LEN + go] = tl[0][tx][ty];
    g_gin[(size_t)(1*NB + b)*T_LEN + go] = tl[1][tx][ty];
    g_gin[(size_t)(2*NB + b)*T_LEN + go] = tl[2][tx][ty];
}

// ---------------- nonlinear smoothing: coalesced L2-layout register loop ----------------
template<bool USEMIN, bool STORE, bool LIM>
__device__ __forceinline__ float sm_seg(const float* __restrict__ sp, float* __restrict__ dp,
                                        bool act, float f, float at, float rt,
                                        float A1, float A2, float lt, float initv)
{
    float ring[32];
#pragma unroll
    for (int j = 0; j < 32; ++j) ring[j] = act ? __ldg(sp + j*32) : initv;
    for (int bs = 0; bs < SM_CH; bs += 32) {
#pragma unroll
        for (int j = 0; j < 32; ++j) {
            float g = ring[j];
            int nx = bs + 32 + j;
            ring[j] = (act && nx < SM_CH) ? __ldg(sp + nx*32) : initv;
            float u = fmaf(A1, f, at * g);
            float v = fmaf(A2, f, rt * g);
            f = USEMIN ? fminf(u, v) : fmaxf(u, v);
            if (STORE) {
                float o = f;
                if (LIM) o = fminf(1.f, __fdividef(lt, fmaxf(f, 1e-7f)));
                dp[(bs + j)*32] = o;
            }
        }
    }
    return act ? f : initv;   // exact-reset lanes that were inactive
}

template<bool USEMIN, bool LIM>
__device__ __forceinline__ void sm_run(const float* __restrict__ src, float* __restrict__ dst,
                                       int c, float at, float rt, float lt, float initv)
{
    float A1 = 1.f - at, A2 = 1.f - rt;
    float f = initv;
#pragma unroll
    for (int seg = 0; seg < 4; ++seg) {
        int cc = c - 4 + seg;
        f = sm_seg<USEMIN, false, false>(src + cc, dst, cc >= 0, f, at, rt, A1, A2, lt, initv);
    }
    sm_seg<USEMIN, true, LIM>(src + c, dst + c, true, f, at, rt, A1, A2, lt, initv);
}

__global__ void k_smooth_band()
{
    int seq = blockIdx.x, c = threadIdx.x;   // 48 blocks x 32 threads
    BSM p = d_bsm[seq];
    const float* src = g_gin + (size_t)seq * T_LEN;
    float*       dst = g_gsm + (size_t)seq * T_LEN;
    if (p.useMin) sm_run<true,  false>(src, dst, c, p.at, p.rt, 0.f, 1.f);
    else          sm_run<false, false>(src, dst, c, p.at, p.rt, 0.f, 1.f);
}

__global__ void k_smooth_lim()
{
    int b = blockIdx.x, c = threadIdx.x;     // 16 blocks x 32 threads
    LSM p = d_lsm[b];
    const float* src = g_det + (size_t)b * T_LEN;
    float*       dst = g_lg  + (size_t)b * T_LEN;
    if (p.useMin) sm_run<true,  true>(src, dst, c, p.at, p.rt, p.lt, 0.f);
    else          sm_run<false, true>(src, dst, c, p.at, p.rt, p.lt, 0.f);
}

// ---------------- band mix + limiter detector ----------------
__global__ void k_mix()
{
    __shared__ float tg[3][32][33];
    __shared__ float td[32][33];
    int i0 = blockIdx.x * 32;
    int b  = blockIdx.y;
    int tx = threadIdx.x, ty = threadIdx.y;

    size_t gi = (size_t)(i0 + ty)*32 + tx;   // L2-layout coalesced read of gsm
    tg[0][tx][ty] = g_gsm[(size_t)(0*NB + b)*T_LEN + gi];
    tg[1][tx][ty] = g_gsm[(size_t)(1*NB + b)*T_LEN + gi];
    tg[2][tx][ty] = g_gsm[(size_t)(2*NB + b)*T_LEN + gi];
    __syncthreads();

    int t = ty*SM_CH + i0 + tx;
    size_t base = (size_t)b * (NCHA*T_LEN) + t;
    float x0 = g_xd [base], x1 = g_xd [base + T_LEN];
    float l0 = g_low[base], l1 = g_low[base + T_LEN];
    float h0 = g_high[base], h1 = g_high[base + T_LEN];
    float gl = tg[0][ty][tx], gm = tg[1][ty][tx], gh = tg[2][ty][tx];
    float mb = d_mb[b], om = 1.f - mb;
    float mid0 = x0 - l0 - h0;
    float y0 = l0*gl + mid0*gm + h0*gh;
    float a0 = mb*y0 + om*x0;
    float mid1 = x1 - l1 - h1;
    float y1 = l1*gl + mid1*gm + h1*gh;
    float a1 = mb*y1 + om*x1;
    g_xm[base]         = a0;
    g_xm[base + T_LEN] = a1;
    td[ty][tx] = fabsf(a0 + a1);
    __syncthreads();
    g_det[(size_t)b*T_LEN + gi] = td[tx][ty];
}

// ---------------- final limiter application ----------------
__global__ void k_final(float* __restrict__ out)
{
    __shared__ float tg[32][33];
    int i0 = blockIdx.x * 32;
    int b  = blockIdx.y;
    int tx = threadIdx.x, ty = threadIdx.y;
    size_t gi = (size_t)(i0 + ty)*32 + tx;
    tg[tx][ty] = g_lg[(size_t)b*T_LEN + gi];
    __syncthreads();
    int t = ty*SM_CH + i0 + tx;
    size_t base = (size_t)b * (NCHA*T_LEN) + t;
    float g = tg[ty][tx];
    out[base]         = g_xm[base]         * g;
    out[base + T_LEN] = g_xm[base + T_LEN] * g;
}

// ---------------- launcher ----------------
extern "C" void kernel_launch(void* const* d_in, const int* in_sizes, int n_in,
                              void* d_out, int out_size)
{
    const float* x     = (const float*)d_in[0];
    const float* drive = (const float*)d_in[1];
    const float* dmix  = (const float*)d_in[2];
    const float* locut = (const float*)d_in[3];
    const float* hicut = (const float*)d_in[4];
    const float* mbmix = (const float*)d_in[5];
    const float* ct    = (const float*)d_in[6];
    const float* cr    = (const float*)d_in[7];
    const float* et    = (const float*)d_in[8];
    const float* er    = (const float*)d_in[9];
    const float* atms  = (const float*)d_in[10];
    const float* rtms  = (const float*)d_in[11];
    const float* lth   = (const float*)d_in[12];
    const float* lat   = (const float*)d_in[13];
    const float* lrt   = (const float*)d_in[14];
    (void)in_sizes; (void)n_in; (void)out_size;

    dim3 tile(32, 32);
    dim3 g2(128, NB);

    k_setup<<<1, 64>>>(drive, dmix, locut, hicut, mbmix, ct, cr, et, er,
                       atms, rtms, lth, lat, lrt);
    k_dist<<<(NSEQ*T_LEN/4 + 255)/256, 256>>>(x);
    k_bq_pass0<<<64, BQ_NT>>>();
    k_bq_pass1<<<64, BQ_NT>>>();
    k_bandgain<<<g2, tile>>>();
    k_smooth_band<<<NBS, 32>>>();
    k_mix<<<g2, tile>>>();
    k_smooth_lim<<<NB, 32>>>();
    k_final<<<g2, tile>>>((float*)d_out);
}

// round 6
// speedup vs baseline: 3.3798x; 1.0005x over previous
#include <cuda_runtime.h>
#include <math.h>

// ---------------- problem constants ----------------
#define T_LEN 131072
#define NB 16
#define NCHA 2
#define NSEQ (NB*NCHA)
#define NBAND 3
#define NBS (NBAND*NB)
#define SRATE 44100.0f

// biquad config: 256 threads x 512-sample chunks
#define BQ_NT 256
#define BQ_C 512
#define BQ_LEV 8

// smoother config: 32 chunks of 4096, 16384-sample warmup (4 chunks)
#define SM_CH 4096

// ---------------- scratch ----------------
__device__ float g_xd  [NSEQ*T_LEN];   // distorted input (natural layout)
__device__ float g_t1  [NSEQ*T_LEN];   // low biquad stage1 (B layout: (t%512)*256 + t/512)
__device__ float g_t2  [NSEQ*T_LEN];   // high biquad stage1 (B layout)
__device__ float g_low [NSEQ*T_LEN];   // natural
__device__ float g_high[NSEQ*T_LEN];   // natural
__device__ float g_gin [NBS*T_LEN];    // L2 layout: (t%4096)*32 + t/4096
__device__ float g_gsm [NBS*T_LEN];    // L2 layout
__device__ float g_xm  [NSEQ*T_LEN];   // natural
__device__ float g_det [NB*T_LEN];     // L2 layout
__device__ float g_lg  [NB*T_LEN];     // L2 layout

struct BQ  { float na1, na2, b0, k1, k2; };
struct BSM { float at, rt, ct, sc, et, se; int useMin; };
struct LSM { float at, rt, lt; int useMin; };

__device__ BQ  d_bq[2*NB];
__device__ BSM d_bsm[NBS];      // band-major: seq = band*16 + b
__device__ LSM d_lsm[NB];
__device__ float d_w[NB], d_gd[NB], d_mb[NB];

// ---------------- setup ----------------
__global__ void k_setup(const float* __restrict__ drive, const float* __restrict__ dmix,
                        const float* __restrict__ locut, const float* __restrict__ hicut,
                        const float* __restrict__ mbmix,
                        const float* __restrict__ ct, const float* __restrict__ cr,
                        const float* __restrict__ et, const float* __restrict__ er,
                        const float* __restrict__ atms, const float* __restrict__ rtms,
                        const float* __restrict__ lth, const float* __restrict__ lat,
                        const float* __restrict__ lrt)
{
    int i = threadIdx.x;
    if (i < NB) {
        d_w[i]  = dmix[i];
        d_gd[i] = exp2f(drive[i] * 0.16609640474436813f);
        d_mb[i] = mbmix[i];
        for (int f = 0; f < 2; ++f) {
            double cut = (f == 0) ? (double)locut[i] : (double)hicut[i];
            double w0 = 2.0 * 3.14159265358979323846 * cut / 44100.0;
            double al = sin(w0) * 0.70710678118654752;
            double c  = cos(w0);
            double b0, b1, b2;
            if (f == 0) { b0 = (1.0 - c) * 0.5; b1 = 1.0 - c;    b2 = (1.0 - c) * 0.5; }
            else        { b0 = (1.0 + c) * 0.5; b1 = -(1.0 + c); b2 = (1.0 + c) * 0.5; }
            double a0 = 1.0 + al;
            b0 /= a0; b1 /= a0; b2 /= a0;
            double a1 = -2.0 * c / a0, a2 = (1.0 - al) / a0;
            BQ q;
            q.na1 = (float)(-a1); q.na2 = (float)(-a2); q.b0 = (float)b0;
            q.k1  = (float)(b1 - a1 * b0);
            q.k2  = (float)(b2 - a2 * b0);
            d_bq[f*NB + i] = q;
        }
        float at = 1.f - expf(-2200.f / (lat[i] * SRATE));
        float rt = 1.f - expf(-2200.f / (lrt[i] * SRATE));
        LSM l; l.at = at; l.rt = rt;
        l.lt = exp2f(lth[i] * 0.16609640474436813f);
        l.useMin = (at < rt);
        d_lsm[i] = l;
    }
    if (i < NBS) {
        int band = i / NB, b = i % NB;
        int idx = b*3 + band;
        float at = 1.f - expf(-2200.f / (atms[idx] * SRATE));
        float rt = 1.f - expf(-2200.f / (rtms[idx] * SRATE));
        BSM s;
        s.at = at; s.rt = rt; s.useMin = (at >= rt);
        s.ct = ct[idx]; s.sc = 1.f - 1.f / cr[idx];
        s.et = et[idx]; s.se = 1.f - 1.f / er[idx];
        d_bsm[i] = s;
    }
}

// ---------------- distortion ----------------
__global__ void k_dist(const float* __restrict__ x)
{
    int idx = blockIdx.x * blockDim.x + threadIdx.x;
    const int n4 = NSEQ * T_LEN / 4;
    if (idx >= n4) return;
    int b = idx >> 16;
    float w = d_w[b], gd = d_gd[b], ow = 1.f - w;
    float4 v = __ldg(((const float4*)x) + idx);
#define TLANE(L) { \
    float z = fminf(fmaxf(v.L * gd, -40.f), 40.f); \
    float e = __expf(2.f * z); \
    float th = __fdividef(e - 1.f, e + 1.f); \
    v.L = fmaf(w, th, ow * v.L); }
    TLANE(x) TLANE(y) TLANE(z) TLANE(w)
#undef TLANE
    ((float4*)g_xd)[idx] = v;
}

// ---------------- biquad core ----------------
__device__ __forceinline__ void bqstep(float x, float& z1, float& z2, const BQ& c)
{
    float t  = fmaf(c.k1, x, z2);
    float n2 = fmaf(c.na2, z1, c.k2 * x);
    z1 = fmaf(c.na1, z1, t);
    z2 = n2;
}
__device__ __forceinline__ float bqstep_y(float x, float& z1, float& z2, const BQ& c)
{
    float y  = fmaf(c.b0, x, z1);
    float t  = fmaf(c.k1, x, z2);
    float n2 = fmaf(c.na2, z1, c.k2 * x);
    z1 = fmaf(c.na1, z1, t);
    z2 = n2;
    return y;
}

__device__ __forceinline__ void bq_make_sP(const BQ& cf, float sP[BQ_LEV][4])
{
    // A = [[na1,1],[na2,0]] ; A^512 then successive squarings
    double m00 = (double)cf.na1, m01 = 1.0, m10 = (double)cf.na2, m11 = 0.0;
    for (int k = 0; k < 9; ++k) {
        double t00 = m00*m00 + m01*m10, t01 = m00*m01 + m01*m11;
        double t10 = m10*m00 + m11*m10, t11 = m10*m01 + m11*m11;
        m00 = t00; m01 = t01; m10 = t10; m11 = t11;
    }
    for (int lv = 0; lv < BQ_LEV; ++lv) {
        sP[lv][0] = (float)m00; sP[lv][1] = (float)m01;
        sP[lv][2] = (float)m10; sP[lv][3] = (float)m11;
        double t00 = m00*m00 + m01*m10, t01 = m00*m01 + m01*m11;
        double t10 = m10*m00 + m11*m10, t11 = m10*m01 + m11*m11;
        m00 = t00; m01 = t01; m10 = t10; m11 = t11;
    }
}

// pass 0: reads g_xd (natural) via smem transpose tiles, writes t1/t2 in B layout
__global__ void k_bq_pass0()
{
    __shared__ float  sT[8][32][33];
    __shared__ float2 sF[BQ_NT];
    __shared__ float  sP[BQ_LEV][4];
    int blk = blockIdx.x;
    int f = blk >> 5, s = blk & 31, b = s >> 1;
    const float* in = g_xd + (size_t)s * T_LEN;
    float* out = (f ? g_t2 : g_t1) + (size_t)s * T_LEN;
    BQ cf = d_bq[f*NB + b];
    int tid = threadIdx.x, w = tid >> 5, l = tid & 31;

    if (tid == 0) bq_make_sP(cf, sP);

    const float* wbase = in + (size_t)(w*32) * BQ_C;   // rows r: +r*512

    float nv[32];
#pragma unroll
    for (int r = 0; r < 32; ++r) nv[r] = __ldg(wbase + r*BQ_C + l);

    // phase A: state only
    float z1 = 0.f, z2 = 0.f;
    for (int tile = 0; tile < 16; ++tile) {
        __syncwarp();
#pragma unroll
        for (int r = 0; r < 32; ++r) sT[w][r][l] = nv[r];
        __syncwarp();
        if (tile < 15) {
#pragma unroll
            for (int r = 0; r < 32; ++r) nv[r] = __ldg(wbase + r*BQ_C + (tile+1)*32 + l);
        }
#pragma unroll
        for (int i = 0; i < 32; ++i) { float xv = sT[w][l][i]; bqstep(xv, z1, z2, cf); }
    }
    __syncthreads();

    // Kogge-Stone scan over 256 chunk states
    float2 my = make_float2(z1, z2);
#pragma unroll
    for (int lv = 0; lv < BQ_LEV; ++lv) {
        sF[tid] = my;
        __syncthreads();
        int d = 1 << lv;
        if (tid >= d) {
            float2 o = sF[tid - d];
            my.x += sP[lv][0]*o.x + sP[lv][1]*o.y;
            my.y += sP[lv][2]*o.x + sP[lv][3]*o.y;
        }
        __syncthreads();
    }
    sF[tid] = my;
    __syncthreads();
    float2 e = (tid > 0) ? sF[tid-1] : make_float2(0.f, 0.f);

    // phase B: regenerate with true state, emit B-layout (coalesced)
    z1 = e.x; z2 = e.y;
#pragma unroll
    for (int r = 0; r < 32; ++r) nv[r] = __ldg(wbase + r*BQ_C + l);
    for (int tile = 0; tile < 16; ++tile) {
        __syncwarp();
#pragma unroll
        for (int r = 0; r < 32; ++r) sT[w][r][l] = nv[r];
        __syncwarp();
        if (tile < 15) {
#pragma unroll
            for (int r = 0; r < 32; ++r) nv[r] = __ldg(wbase + r*BQ_C + (tile+1)*32 + l);
        }
#pragma unroll
        for (int i = 0; i < 32; ++i) {
            float xv = sT[w][l][i];
            float y = bqstep_y(xv, z1, z2, cf);
            out[(size_t)(tile*32 + i)*BQ_NT + tid] = y;
        }
    }
}

// pass 1: reads t1/t2 (B layout, coalesced + register ring), writes low/high natural via smem tiles
__global__ void k_bq_pass1()
{
    __shared__ float  sO[8][32][33];
    __shared__ float2 sF[BQ_NT];
    __shared__ float  sP[BQ_LEV][4];
    int blk = blockIdx.x;
    int f = blk >> 5, s = blk & 31, b = s >> 1;
    const float* in = (f ? g_t2 : g_t1) + (size_t)s * T_LEN;
    float* out = (f ? g_high : g_low) + (size_t)s * T_LEN;
    BQ cf = d_bq[f*NB + b];
    int tid = threadIdx.x, w = tid >> 5, l = tid & 31;

    if (tid == 0) bq_make_sP(cf, sP);

    // phase A
    float ring[32];
#pragma unroll
    for (int j = 0; j < 32; ++j) ring[j] = __ldg(in + j*BQ_NT + tid);
    float z1 = 0.f, z2 = 0.f;
    for (int base = 0; base < BQ_C; base += 32) {
#pragma unroll
        for (int j = 0; j < 32; ++j) {
            float xv = ring[j];
            int nx = base + 32 + j;
            if (nx < BQ_C) ring[j] = __ldg(in + nx*BQ_NT + tid);
            bqstep(xv, z1, z2, cf);
        }
    }
    __syncthreads();

    float2 my = make_float2(z1, z2);
#pragma unroll
    for (int lv = 0; lv < BQ_LEV; ++lv) {
        sF[tid] = my;
        __syncthreads();
        int d = 1 << lv;
        if (tid >= d) {
            float2 o = sF[tid - d];
            my.x += sP[lv][0]*o.x + sP[lv][1]*o.y;
            my.y += sP[lv][2]*o.x + sP[lv][3]*o.y;
        }
        __syncthreads();
    }
    sF[tid] = my;
    __syncthreads();
    float2 e = (tid > 0) ? sF[tid-1] : make_float2(0.f, 0.f);

    // phase B
    z1 = e.x; z2 = e.y;
#pragma unroll
    for (int j = 0; j < 32; ++j) ring[j] = __ldg(in + j*BQ_NT + tid);
    float* wout = out + (size_t)(w*32) * BQ_C;
    for (int tile = 0; tile < 16; ++tile) {
#pragma unroll
        for (int j = 0; j < 32; ++j) {
            float xv = ring[j];
            int nx = tile*32 + 32 + j;
            if (nx < BQ_C) ring[j] = __ldg(in + nx*BQ_NT + tid);
            float y = bqstep_y(xv, z1, z2, cf);
            sO[w][l][j] = y;
        }
        __syncwarp();
#pragma unroll
        for (int r = 0; r < 32; ++r) wout[r*BQ_C + tile*32 + l] = sO[w][r][l];
        __syncwarp();
    }
}

// ---------------- instantaneous band gain (natural reads -> L2-layout writes) ----------------
__device__ __forceinline__ float comp_gain(float det, const BSM& p)
{
    float xdb = 6.0205999132796239f * __log2f(fmaxf(det, 1e-7f));
    float gdb = fminf(fminf(p.sc * (p.ct - xdb), p.se * (p.et - xdb)), 0.f);
    return exp2f(gdb * 0.16609640474436813f);
}

__global__ void k_bandgain()
{
    __shared__ float tl[3][32][33];
    int i0 = blockIdx.x * 32;
    int b  = blockIdx.y;
    int tx = threadIdx.x, ty = threadIdx.y;
    int t = ty*SM_CH + i0 + tx;
    size_t base = (size_t)b * (NCHA*T_LEN) + t;
    float x0 = g_xd [base], x1 = g_xd [base + T_LEN];
    float l0 = g_low[base], l1 = g_low[base + T_LEN];
    float h0 = g_high[base], h1 = g_high[base + T_LEN];
    float ls = l0 + l1, hs = h0 + h1, xs = x0 + x1;
    BSM pl = d_bsm[0*NB + b], pm = d_bsm[1*NB + b], ph = d_bsm[2*NB + b];
    tl[0][ty][tx] = comp_gain(fabsf(ls), pl);
    tl[1][ty][tx] = comp_gain(fabsf(xs - ls - hs), pm);
    tl[2][ty][tx] = comp_gain(fabsf(hs), ph);
    __syncthreads();
    size_t go = (size_t)(i0 + ty)*32 + tx;   // L2 layout
    g_gin[(size_t)(0*NB + b)*T_LEN + go] = tl[0][tx][ty];
    g_gin[(size_t)(1*NB + b)*T_LEN + go] = tl[1][tx][ty];
    g_gin[(size_t)(2*NB + b)*T_LEN + go] = tl[2][tx][ty];
}

// ---------------- nonlinear smoothing: coalesced L2-layout register loop ----------------
template<bool USEMIN, bool STORE, bool LIM>
__device__ __forceinline__ float sm_seg(const float* __restrict__ sp, float* __restrict__ dp,
                                        bool act, float f, float at, float rt,
                                        float A1, float A2, float lt, float initv)
{
    float ring[32];
#pragma unroll
    for (int j = 0; j < 32; ++j) ring[j] = act ? __ldg(sp + j*32) : initv;
    for (int bs = 0; bs < SM_CH; bs += 32) {
#pragma unroll
        for (int j = 0; j < 32; ++j) {
            float g = ring[j];
            int nx = bs + 32 + j;
            ring[j] = (act && nx < SM_CH) ? __ldg(sp + nx*32) : initv;
            float u = fmaf(A1, f, at * g);
            float v = fmaf(A2, f, rt * g);
            f = USEMIN ? fminf(u, v) : fmaxf(u, v);
            if (STORE) {
                float o = f;
                if (LIM) o = fminf(1.f, __fdividef(lt, fmaxf(f, 1e-7f)));
                dp[(bs + j)*32] = o;
            }
        }
    }
    return act ? f : initv;   // exact-reset lanes that were inactive
}

template<bool USEMIN, bool LIM>
__device__ __forceinline__ void sm_run(const float* __restrict__ src, float* __restrict__ dst,
                                       int c, float at, float rt, float lt, float initv)
{
    float A1 = 1.f - at, A2 = 1.f - rt;
    float f = initv;
#pragma unroll
    for (int seg = 0; seg < 4; ++seg) {
        int cc = c - 4 + seg;
        f = sm_seg<USEMIN, false, false>(src + cc, dst, cc >= 0, f, at, rt, A1, A2, lt, initv);
    }
    sm_seg<USEMIN, true, LIM>(src + c, dst + c, true, f, at, rt, A1, A2, lt, initv);
}

__global__ void k_smooth_band()
{
    int seq = blockIdx.x, c = threadIdx.x;   // 48 blocks x 32 threads
    BSM p = d_bsm[seq];
    const float* src = g_gin + (size_t)seq * T_LEN;
    float*       dst = g_gsm + (size_t)seq * T_LEN;
    if (p.useMin) sm_run<true,  false>(src, dst, c, p.at, p.rt, 0.f, 1.f);
    else          sm_run<false, false>(src, dst, c, p.at, p.rt, 0.f, 1.f);
}

__global__ void k_smooth_lim()
{
    int b = blockIdx.x, c = threadIdx.x;     // 16 blocks x 32 threads
    LSM p = d_lsm[b];
    const float* src = g_det + (size_t)b * T_LEN;
    float*       dst = g_lg  + (size_t)b * T_LEN;
    if (p.useMin) sm_run<true,  true>(src, dst, c, p.at, p.rt, p.lt, 0.f);
    else          sm_run<false, true>(src, dst, c, p.at, p.rt, p.lt, 0.f);
}

// ---------------- band mix + limiter detector ----------------
__global__ void k_mix()
{
    __shared__ float tg[3][32][33];
    __shared__ float td[32][33];
    int i0 = blockIdx.x * 32;
    int b  = blockIdx.y;
    int tx = threadIdx.x, ty = threadIdx.y;

    size_t gi = (size_t)(i0 + ty)*32 + tx;   // L2-layout coalesced read of gsm
    tg[0][tx][ty] = g_gsm[(size_t)(0*NB + b)*T_LEN + gi];
    tg[1][tx][ty] = g_gsm[(size_t)(1*NB + b)*T_LEN + gi];
    tg[2][tx][ty] = g_gsm[(size_t)(2*NB + b)*T_LEN + gi];
    __syncthreads();

    int t = ty*SM_CH + i0 + tx;
    size_t base = (size_t)b * (NCHA*T_LEN) + t;
    float x0 = g_xd [base], x1 = g_xd [base + T_LEN];
    float l0 = g_low[base], l1 = g_low[base + T_LEN];
    float h0 = g_high[base], h1 = g_high[base + T_LEN];
    float gl = tg[0][ty][tx], gm = tg[1][ty][tx], gh = tg[2][ty][tx];
    float mb = d_mb[b], om = 1.f - mb;
    float mid0 = x0 - l0 - h0;
    float y0 = l0*gl + mid0*gm + h0*gh;
    float a0 = mb*y0 + om*x0;
    float mid1 = x1 - l1 - h1;
    float y1 = l1*gl + mid1*gm + h1*gh;
    float a1 = mb*y1 + om*x1;
    g_xm[base]         = a0;
    g_xm[base + T_LEN] = a1;
    td[ty][tx] = fabsf(a0 + a1);
    __syncthreads();
    g_det[(size_t)b*T_LEN + gi] = td[tx][ty];
}

// ---------------- final limiter application ----------------
__global__ void k_final(float* __restrict__ out)
{
    __shared__ float tg[32][33];
    int i0 = blockIdx.x * 32;
    int b  = blockIdx.y;
    int tx = threadIdx.x, ty = threadIdx.y;
    size_t gi = (size_t)(i0 + ty)*32 + tx;
    tg[tx][ty] = g_lg[(size_t)b*T_LEN + gi];
    __syncthreads();
    int t = ty*SM_CH + i0 + tx;
    size_t base = (size_t)b * (NCHA*T_LEN) + t;
    float g = tg[ty][tx];
    out[base]         = g_xm[base]         * g;
    out[base + T_LEN] = g_xm[base + T_LEN] * g;
}

// ---------------- launcher ----------------
extern "C" void kernel_launch(void* const* d_in, const int* in_sizes, int n_in,
                              void* d_out, int out_size)
{
    const float* x     = (const float*)d_in[0];
    const float* drive = (const float*)d_in[1];
    const float* dmix  = (const float*)d_in[2];
    const float* locut = (const float*)d_in[3];
    const float* hicut = (const float*)d_in[4];
    const float* mbmix = (const float*)d_in[5];
    const float* ct    = (const float*)d_in[6];
    const float* cr    = (const float*)d_in[7];
    const float* et    = (const float*)d_in[8];
    const float* er    = (const float*)d_in[9];
    const float* atms  = (const float*)d_in[10];
    const float* rtms  = (const float*)d_in[11];
    const float* lth   = (const float*)d_in[12];
    const float* lat   = (const float*)d_in[13];
    const float* lrt   = (const float*)d_in[14];
    (void)in_sizes; (void)n_in; (void)out_size;

    dim3 tile(32, 32);
    dim3 g2(128, NB);

    k_setup<<<1, 64>>>(drive, dmix, locut, hicut, mbmix, ct, cr, et, er,
                       atms, rtms, lth, lat, lrt);
    k_dist<<<(NSEQ*T_LEN/4 + 255)/256, 256>>>(x);
    k_bq_pass0<<<64, BQ_NT>>>();
    k_bq_pass1<<<64, BQ_NT>>>();
    k_bandgain<<<g2, tile>>>();
    k_smooth_band<<<NBS, 32>>>();
    k_mix<<<g2, tile>>>();
    k_smooth_lim<<<NB, 32>>>();
    k_final<<<g2, tile>>>((float*)d_out);
}

// round 7
// speedup vs baseline: 4.8189x; 1.4258x over previous
#include <cuda_runtime.h>
#include <math.h>

#define T_LEN 131072
#define NB 16
#define NCHA 2
#define NSEQ (NB*NCHA)
#define NBS 48
#define DB2L 0.16609640474436813f   // log2(10)/20

// L layout: addr(t) = (t % 1024)*128 + t/1024   (128 chunks of 1024)
#define LCH 1024
#define LNC 128

// biquad: 512 threads x 256-sample chunks, scan over 512
#define BQ_NT 512
#define BQ_C 256
#define BQ_LEV 9

// smoother: 128 chunks of 1024, 16-chunk warmup
#define SM_W 16

__device__ float g_xd  [NSEQ*T_LEN];   // L
__device__ float g_low [NSEQ*T_LEN];   // L
__device__ float g_high[NSEQ*T_LEN];   // L
__device__ float g_gin [NBS*T_LEN];    // L
__device__ float g_gsm [NBS*T_LEN];    // L
__device__ float g_xm  [NSEQ*T_LEN];   // L
__device__ float g_det [NB*T_LEN];     // L
__device__ float g_lg  [NB*T_LEN];     // L

struct BQ { float na1, na2, b0, k1, k2; };

__device__ __forceinline__ float f_lg2(float x){ float r; asm("lg2.approx.f32 %0,%1;":"=f"(r):"f"(x)); return r; }
__device__ __forceinline__ float f_ex2(float x){ float r; asm("ex2.approx.f32 %0,%1;":"=f"(r):"f"(x)); return r; }

// ---------------- dist: natural -> L, tanh drive mix ----------------
__global__ void k_dist(const float* __restrict__ x, const float* __restrict__ drive,
                       const float* __restrict__ dmix)
{
    __shared__ float sT[32][33];
    __shared__ float sw, sgd;
    int s = blockIdx.y, b = s >> 1;
    int bx = blockIdx.x;
    int c0 = (bx >> 5) * 32, tp0 = (bx & 31) * 32;
    int tx = threadIdx.x, ty = threadIdx.y;
    if (tx == 0 && ty == 0) { sw = dmix[b]; sgd = exp2f(drive[b] * DB2L); }
    __syncthreads();
    float w = sw, gd = sgd, ow = 1.f - w;
    int t = (c0 + ty) * LCH + tp0 + tx;                    // natural, contiguous in tx
    float v = __ldg(x + (size_t)s * T_LEN + t);
    float z = fminf(fmaxf(v * gd, -15.f), 15.f);
    float e = __expf(2.f * z);
    float th = __fdividef(e - 1.f, e + 1.f);
    v = fmaf(w, th, ow * v);
    sT[ty][tx] = v;
    __syncthreads();
    size_t go = (size_t)(tp0 + ty) * LNC + c0 + tx;        // L, contiguous in tx
    g_xd[(size_t)s * T_LEN + go] = sT[tx][ty];
}

// ---------------- fused LR4 biquad (both stages, one block per (filter,seq)) ----------------
__device__ __forceinline__ void bqstep(float x, float& z1, float& z2, const BQ& c)
{
    float t  = fmaf(c.k1, x, z2);
    float n2 = fmaf(c.na2, z1, c.k2 * x);
    z1 = fmaf(c.na1, z1, t);
    z2 = n2;
}
__device__ __forceinline__ float bqstep_y(float x, float& z1, float& z2, const BQ& c)
{
    float y  = fmaf(c.b0, x, z1);
    float t  = fmaf(c.k1, x, z2);
    float n2 = fmaf(c.na2, z1, c.k2 * x);
    z1 = fmaf(c.na1, z1, t);
    z2 = n2;
    return y;
}

__device__ __forceinline__ float2 ks_scan(float2 my, float2* sF, float (*sP)[4], int tid)
{
    __syncthreads();
#pragma unroll
    for (int lv = 0; lv < BQ_LEV; ++lv) {
        sF[tid] = my;
        __syncthreads();
        int d = 1 << lv;
        if (tid >= d) {
            float2 o = sF[tid - d];
            my.x += sP[lv][0]*o.x + sP[lv][1]*o.y;
            my.y += sP[lv][2]*o.x + sP[lv][3]*o.y;
        }
        __syncthreads();
    }
    sF[tid] = my;
    __syncthreads();
    float2 e = (tid > 0) ? sF[tid-1] : make_float2(0.f, 0.f);
    __syncthreads();
    return e;
}

__global__ void k_bq(const float* __restrict__ locut, const float* __restrict__ hicut)
{
    __shared__ float2 sF[BQ_NT];
    __shared__ float  sP[BQ_LEV][4];
    __shared__ BQ     sCF;
    int blk = blockIdx.x;
    int f = blk >> 5, s = blk & 31, b = s >> 1;
    const float* in = g_xd + (size_t)s * T_LEN;
    float* out = (f ? g_high : g_low) + (size_t)s * T_LEN;
    int tid = threadIdx.x;

    if (tid == 0) {
        double cut = f ? (double)hicut[b] : (double)locut[b];
        double w0 = 2.0 * 3.14159265358979323846 * cut / 44100.0;
        double al = sin(w0) * 0.70710678118654752;
        double c  = cos(w0);
        double b0, b1, b2;
        if (f == 0) { b0 = (1.0 - c)*0.5; b1 = 1.0 - c;    b2 = (1.0 - c)*0.5; }
        else        { b0 = (1.0 + c)*0.5; b1 = -(1.0 + c); b2 = (1.0 + c)*0.5; }
        double a0 = 1.0 + al;
        b0 /= a0; b1 /= a0; b2 /= a0;
        double a1 = -2.0*c/a0, a2 = (1.0 - al)/a0;
        sCF.na1 = (float)(-a1); sCF.na2 = (float)(-a2); sCF.b0 = (float)b0;
        sCF.k1 = (float)(b1 - a1*b0); sCF.k2 = (float)(b2 - a2*b0);
        double m00 = -a1, m01 = 1.0, m10 = -a2, m11 = 0.0;
        for (int k = 0; k < 8; ++k) {          // A^256
            double t00 = m00*m00 + m01*m10, t01 = m00*m01 + m01*m11;
            double t10 = m10*m00 + m11*m10, t11 = m10*m01 + m11*m11;
            m00 = t00; m01 = t01; m10 = t10; m11 = t11;
        }
        for (int lv = 0; lv < BQ_LEV; ++lv) {
            sP[lv][0] = (float)m00; sP[lv][1] = (float)m01;
            sP[lv][2] = (float)m10; sP[lv][3] = (float)m11;
            double t00 = m00*m00 + m01*m10, t01 = m00*m01 + m01*m11;
            double t10 = m10*m00 + m11*m10, t11 = m10*m01 + m11*m11;
            m00 = t00; m01 = t01; m10 = t10; m11 = t11;
        }
    }
    __syncthreads();
    BQ cf = sCF;
    // thread chunk [tid*256, tid*256+256): L addr = ((tid&3)*256 + j)*128 + tid/4
    int base = ((tid & 3) * 256) * LNC + (tid >> 2);
    const float* ip = in + base;
    float ring[32];

    // phase A1: stage-1 zero-state
    float z1 = 0.f, z2 = 0.f;
#pragma unroll
    for (int j = 0; j < 32; ++j) ring[j] = __ldg(ip + j*LNC);
    for (int bs = 0; bs < BQ_C; bs += 32) {
#pragma unroll
        for (int j = 0; j < 32; ++j) {
            float xv = ring[j];
            int nx = bs + 32 + j;
            if (nx < BQ_C) ring[j] = __ldg(ip + nx*LNC);
            bqstep(xv, z1, z2, cf);
        }
    }
    float2 e1 = ks_scan(make_float2(z1, z2), sF, sP, tid);

    // phase B1+A2: stage-1 regenerated -> stage-2 zero-state
    z1 = e1.x; z2 = e1.y;
    float w1 = 0.f, w2 = 0.f;
#pragma unroll
    for (int j = 0; j < 32; ++j) ring[j] = __ldg(ip + j*LNC);
    for (int bs = 0; bs < BQ_C; bs += 32) {
#pragma unroll
        for (int j = 0; j < 32; ++j) {
            float xv = ring[j];
            int nx = bs + 32 + j;
            if (nx < BQ_C) ring[j] = __ldg(ip + nx*LNC);
            float y = bqstep_y(xv, z1, z2, cf);
            bqstep(y, w1, w2, cf);
        }
    }
    float2 e2 = ks_scan(make_float2(w1, w2), sF, sP, tid);

    // phase B1+B2: emit
    z1 = e1.x; z2 = e1.y; w1 = e2.x; w2 = e2.y;
#pragma unroll
    for (int j = 0; j < 32; ++j) ring[j] = __ldg(ip + j*LNC);
    float* op = out + base;
    for (int bs = 0; bs < BQ_C; bs += 32) {
#pragma unroll
        for (int j = 0; j < 32; ++j) {
            float xv = ring[j];
            int nx = bs + 32 + j;
            if (nx < BQ_C) ring[j] = __ldg(ip + nx*LNC);
            float y = bqstep_y(xv, z1, z2, cf);
            op[(bs + j)*LNC] = bqstep_y(y, w1, w2, cf);
        }
    }
}

// ---------------- band gain: pure elementwise on L layout ----------------
struct GP { float ct, sc, et, se; };
__device__ __forceinline__ float comp_gain(float det, const GP& p)
{
    float xdb = 6.0205999132796239f * f_lg2(fmaxf(det, 1e-7f));
    float gdb = fminf(fminf(p.sc * (p.ct - xdb), p.se * (p.et - xdb)), 0.f);
    return f_ex2(gdb * DB2L);
}

__global__ void k_bandgain(const float* __restrict__ ct, const float* __restrict__ cr,
                           const float* __restrict__ et, const float* __restrict__ er)
{
    __shared__ GP sp[3];
    int b = blockIdx.y;
    int tid = threadIdx.x;
    if (tid < 3) {
        int idx = b*3 + tid;
        GP g; g.ct = ct[idx]; g.sc = 1.f - 1.f/cr[idx];
        g.et = et[idx]; g.se = 1.f - 1.f/er[idx];
        sp[tid] = g;
    }
    __syncthreads();
    int i = blockIdx.x * blockDim.x + tid;                 // float4 index in plane
    size_t p0 = (size_t)(b*2) * (T_LEN/4), p1 = p0 + T_LEN/4;
    float4 x0 = ((const float4*)g_xd)[p0 + i],  x1 = ((const float4*)g_xd)[p1 + i];
    float4 l0 = ((const float4*)g_low)[p0 + i], l1 = ((const float4*)g_low)[p1 + i];
    float4 h0 = ((const float4*)g_high)[p0 + i],h1 = ((const float4*)g_high)[p1 + i];
    float4 gl, gm, gh;
#define GL(L) { float ls = l0.L + l1.L, hs = h0.L + h1.L, xs = x0.L + x1.L; \
    gl.L = comp_gain(fabsf(ls), sp[0]); \
    gm.L = comp_gain(fabsf(xs - ls - hs), sp[1]); \
    gh.L = comp_gain(fabsf(hs), sp[2]); }
    GL(x) GL(y) GL(z) GL(w)
#undef GL
    ((float4*)g_gin)[(size_t)(0*NB + b)*(T_LEN/4) + i] = gl;
    ((float4*)g_gin)[(size_t)(1*NB + b)*(T_LEN/4) + i] = gm;
    ((float4*)g_gin)[(size_t)(2*NB + b)*(T_LEN/4) + i] = gh;
}

// ---------------- smoothing: chunked + warmup, L-native ----------------
template<bool USEMIN, bool STORE, bool LIM>
__device__ __forceinline__ float sm_seg(const float* __restrict__ sp, float* __restrict__ dp,
                                        bool act, float f, float at, float rt, float lt)
{
    if (!act) return f;
    float A1 = 1.f - at, A2 = 1.f - rt;
    float ring[32];
#pragma unroll
    for (int j = 0; j < 32; ++j) ring[j] = __ldg(sp + j*LNC);
    for (int bs = 0; bs < LCH; bs += 32) {
#pragma unroll
        for (int j = 0; j < 32; ++j) {
            float g = ring[j];
            int nx = bs + 32 + j;
            if (nx < LCH) ring[j] = __ldg(sp + nx*LNC);
            float u = fmaf(A1, f, at * g);
            float v = fmaf(A2, f, rt * g);
            f = USEMIN ? fminf(u, v) : fmaxf(u, v);
            if (STORE) {
                float o = f;
                if (LIM) o = fminf(1.f, __fdividef(lt, fmaxf(f, 1e-7f)));
                dp[(bs + j)*LNC] = o;
            }
        }
    }
    return f;
}

template<bool USEMIN, bool LIM>
__device__ __forceinline__ void sm_run(const float* __restrict__ src, float* __restrict__ dst,
                                       int c, float at, float rt, float lt, float initv)
{
    float f = initv;
    for (int seg = 0; seg < SM_W; ++seg) {
        int cc = c - SM_W + seg;
        f = sm_seg<USEMIN, false, false>(src + cc, dst, cc >= 0, f, at, rt, lt);
    }
    sm_seg<USEMIN, true, LIM>(src + c, dst + c, true, f, at, rt, lt);
}

__global__ void k_smooth_band(const float* __restrict__ atms, const float* __restrict__ rtms)
{
    int seq = blockIdx.x, c = threadIdx.x;      // 48 blocks x 128 threads
    int band = seq >> 4, b = seq & 15;
    int idx = b*3 + band;
    float at = 1.f - __expf(-2200.f / (atms[idx] * 44100.f));
    float rt = 1.f - __expf(-2200.f / (rtms[idx] * 44100.f));
    const float* src = g_gin + (size_t)seq * T_LEN;
    float*       dst = g_gsm + (size_t)seq * T_LEN;
    if (at >= rt) sm_run<true,  false>(src, dst, c, at, rt, 0.f, 1.f);
    else          sm_run<false, false>(src, dst, c, at, rt, 0.f, 1.f);
}

__global__ void k_smooth_lim(const float* __restrict__ lth, const float* __restrict__ lat,
                             const float* __restrict__ lrt)
{
    int b = blockIdx.x, c = threadIdx.x;        // 16 blocks x 128 threads
    float at = 1.f - __expf(-2200.f / (lat[b] * 44100.f));
    float rt = 1.f - __expf(-2200.f / (lrt[b] * 44100.f));
    float lt = exp2f(lth[b] * DB2L);
    const float* src = g_det + (size_t)b * T_LEN;
    float*       dst = g_lg  + (size_t)b * T_LEN;
    if (at <= rt) sm_run<true,  true>(src, dst, c, at, rt, lt, 0.f);
    else          sm_run<false, true>(src, dst, c, at, rt, lt, 0.f);
}

// ---------------- mix + limiter detector: pure elementwise on L ----------------
__global__ void k_mix(const float* __restrict__ mbmix)
{
    int b = blockIdx.y;
    float mb = __ldg(mbmix + b), om = 1.f - mb;
    int i = blockIdx.x * blockDim.x + threadIdx.x;
    size_t p0 = (size_t)(b*2) * (T_LEN/4), p1 = p0 + T_LEN/4;
    float4 x0 = ((const float4*)g_xd)[p0 + i],  x1 = ((const float4*)g_xd)[p1 + i];
    float4 l0 = ((const float4*)g_low)[p0 + i], l1 = ((const float4*)g_low)[p1 + i];
    float4 h0 = ((const float4*)g_high)[p0 + i],h1 = ((const float4*)g_high)[p1 + i];
    float4 gl = ((const float4*)g_gsm)[(size_t)(0*NB + b)*(T_LEN/4) + i];
    float4 gm = ((const float4*)g_gsm)[(size_t)(1*NB + b)*(T_LEN/4) + i];
    float4 gh = ((const float4*)g_gsm)[(size_t)(2*NB + b)*(T_LEN/4) + i];
    float4 m0, m1, dt;
#define ML(L) { \
    float mid0 = x0.L - l0.L - h0.L; \
    float y0 = l0.L*gl.L + mid0*gm.L + h0.L*gh.L; \
    float a0 = mb*y0 + om*x0.L; \
    float mid1 = x1.L - l1.L - h1.L; \
    float y1 = l1.L*gl.L + mid1*gm.L + h1.L*gh.L; \
    float a1 = mb*y1 + om*x1.L; \
    m0.L = a0; m1.L = a1; dt.L = fabsf(a0 + a1); }
    ML(x) ML(y) ML(z) ML(w)
#undef ML
    ((float4*)g_xm)[p0 + i] = m0;
    ((float4*)g_xm)[p1 + i] = m1;
    ((float4*)g_det)[(size_t)b*(T_LEN/4) + i] = dt;
}

// ---------------- final: L -> natural, apply limiter gain ----------------
__global__ void k_final(float* __restrict__ out)
{
    __shared__ float sT[2][32][33];
    int b = blockIdx.y;
    int bx = blockIdx.x;
    int c0 = (bx >> 5) * 32, tp0 = (bx & 31) * 32;
    int tx = threadIdx.x, ty = threadIdx.y;
    size_t A = (size_t)(tp0 + ty) * LNC + c0 + tx;         // L, contiguous in tx
    float g  = g_lg[(size_t)b * T_LEN + A];
    float m0 = g_xm[(size_t)(b*2)   * T_LEN + A] * g;
    float m1 = g_xm[(size_t)(b*2+1) * T_LEN + A] * g;
    sT[0][tx][ty] = m0;
    sT[1][tx][ty] = m1;
    __syncthreads();
    int t = (c0 + ty) * LCH + tp0 + tx;                    // natural, contiguous in tx
    out[(size_t)(b*2)   * T_LEN + t] = sT[0][ty][tx];
    out[(size_t)(b*2+1) * T_LEN + t] = sT[1][ty][tx];
}

// ---------------- launcher ----------------
extern "C" void kernel_launch(void* const* d_in, const int* in_sizes, int n_in,
                              void* d_out, int out_size)
{
    const float* x     = (const float*)d_in[0];
    const float* drive = (const float*)d_in[1];
    const float* dmix  = (const float*)d_in[2];
    const float* locut = (const float*)d_in[3];
    const float* hicut = (const float*)d_in[4];
    const float* mbmix = (const float*)d_in[5];
    const float* ct    = (const float*)d_in[6];
    const float* cr    = (const float*)d_in[7];
    const float* et    = (const float*)d_in[8];
    const float* er    = (const float*)d_in[9];
    const float* atms  = (const float*)d_in[10];
    const float* rtms  = (const float*)d_in[11];
    const float* lth   = (const float*)d_in[12];
    const float* lat   = (const float*)d_in[13];
    const float* lrt   = (const float*)d_in[14];
    (void)in_sizes; (void)n_in; (void)out_size;

    dim3 tile(32, 32);
    k_dist<<<dim3(128, NSEQ), tile>>>(x, drive, dmix);
    k_bq<<<64, BQ_NT>>>(locut, hicut);
    k_bandgain<<<dim3(T_LEN/4/256, NB), 256>>>(ct, cr, et, er);
    k_smooth_band<<<NBS, LNC>>>(atms, rtms);
    k_mix<<<dim3(T_LEN/4/256, NB), 256>>>(mbmix);
    k_smooth_lim<<<NB, LNC>>>(lth, lat, lrt);
    k_final<<<dim3(128, NB), tile>>>((float*)d_out);
}

// round 8
// speedup vs baseline: 6.4336x; 1.3351x over previous
#include <cuda_runtime.h>
#include <math.h>

#define T_LEN 131072
#define NB 16
#define NCHA 2
#define NSEQ (NB*NCHA)
#define NBS 48
#define DB2L 0.16609640474436813f   // log2(10)/20

// P layout (per plane of T_LEN floats): t -> chunk c = t>>10, pos p = t&1023
//   float2 index (c, q=p>>1) = q*128 + c          (128 chunks of 1024 samples)
#define LCH 1024
#define LNC 128
#define QP  512            // pairs per chunk
#define P2  65536          // float2 per plane

// biquad: 512 threads x 256-sample chunks (128 pairs)
#define BQ_NT 512
#define BQ_LEV 9

#define SM_W 16            // warmup chunks (16384 samples)

__device__ float g_xd  [NSEQ*T_LEN];
__device__ float g_low [NSEQ*T_LEN];
__device__ float g_high[NSEQ*T_LEN];
__device__ float g_gin [NBS*T_LEN];
__device__ float g_gsm [NBS*T_LEN];
__device__ float g_xm  [NSEQ*T_LEN];
__device__ float g_det [NB*T_LEN];
__device__ float g_lg  [NB*T_LEN];

struct BQ { float na1, na2, b0, k1, k2; };

__device__ __forceinline__ float f_lg2(float x){ float r; asm("lg2.approx.f32 %0,%1;":"=f"(r):"f"(x)); return r; }
__device__ __forceinline__ float f_ex2(float x){ float r; asm("ex2.approx.f32 %0,%1;":"=f"(r):"f"(x)); return r; }

// ---------------- dist: natural -> P, tanh drive mix ----------------
__global__ void k_dist(const float* __restrict__ x, const float* __restrict__ drive,
                       const float* __restrict__ dmix)
{
    __shared__ float2 sT[32][33];
    __shared__ float sw, sgd;
    int s = blockIdx.y, b = s >> 1;
    int bx = blockIdx.x;
    int c0 = (bx >> 4) * 32, q0 = (bx & 15) * 32;
    int tx = threadIdx.x, ty = threadIdx.y;
    if (tx == 0 && ty == 0) { sw = dmix[b]; sgd = exp2f(drive[b] * DB2L); }
    __syncthreads();
    float w = sw, gd = sgd, ow = 1.f - w;
    const float2* xin = (const float2*)x + (size_t)s * P2;
    float2 v = __ldg(xin + (c0 + ty) * QP + q0 + tx);        // natural (c=c0+ty,q=q0+tx)
#define TL(L) { \
    float z = fminf(fmaxf(v.L * gd, -15.f), 15.f); \
    float e = __expf(2.f * z); \
    float th = __fdividef(e - 1.f, e + 1.f); \
    v.L = fmaf(w, th, ow * v.L); }
    TL(x) TL(y)
#undef TL
    sT[ty][tx] = v;
    __syncthreads();
    float2* xo = (float2*)g_xd + (size_t)s * P2;
    xo[(q0 + ty) * LNC + c0 + tx] = sT[tx][ty];              // P (c=c0+tx,q=q0+ty)
}

// ---------------- fused LR4 biquad ----------------
__device__ __forceinline__ void bqstep(float x, float& z1, float& z2, const BQ& c)
{
    float t  = fmaf(c.k1, x, z2);
    float n2 = fmaf(c.na2, z1, c.k2 * x);
    z1 = fmaf(c.na1, z1, t);
    z2 = n2;
}
__device__ __forceinline__ float bqstep_y(float x, float& z1, float& z2, const BQ& c)
{
    float y  = fmaf(c.b0, x, z1);
    float t  = fmaf(c.k1, x, z2);
    float n2 = fmaf(c.na2, z1, c.k2 * x);
    z1 = fmaf(c.na1, z1, t);
    z2 = n2;
    return y;
}

__device__ __forceinline__ float2 ks_scan(float2 my, float2* sF, float (*sP)[4], int tid)
{
    __syncthreads();
#pragma unroll
    for (int lv = 0; lv < BQ_LEV; ++lv) {
        sF[tid] = my;
        __syncthreads();
        int d = 1 << lv;
        if (tid >= d) {
            float2 o = sF[tid - d];
            my.x += sP[lv][0]*o.x + sP[lv][1]*o.y;
            my.y += sP[lv][2]*o.x + sP[lv][3]*o.y;
        }
        __syncthreads();
    }
    sF[tid] = my;
    __syncthreads();
    float2 e = (tid > 0) ? sF[tid-1] : make_float2(0.f, 0.f);
    __syncthreads();
    return e;
}

__global__ void k_bq(const float* __restrict__ locut, const float* __restrict__ hicut)
{
    __shared__ float2 sF[BQ_NT];
    __shared__ float  sP[BQ_LEV][4];
    __shared__ BQ     sCF;
    int blk = blockIdx.x;
    int f = blk >> 5, s = blk & 31, b = s >> 1;
    const float2* in2 = (const float2*)g_xd + (size_t)s * P2;
    float2* out2 = (float2*)(f ? g_high : g_low) + (size_t)s * P2;
    int tid = threadIdx.x;

    if (tid == 0) {
        double cut = f ? (double)hicut[b] : (double)locut[b];
        double w0 = 2.0 * 3.14159265358979323846 * cut / 44100.0;
        double al = sin(w0) * 0.70710678118654752;
        double c  = cos(w0);
        double b0, b1, b2;
        if (f == 0) { b0 = (1.0 - c)*0.5; b1 = 1.0 - c;    b2 = (1.0 - c)*0.5; }
        else        { b0 = (1.0 + c)*0.5; b1 = -(1.0 + c); b2 = (1.0 + c)*0.5; }
        double a0 = 1.0 + al;
        b0 /= a0; b1 /= a0; b2 /= a0;
        double a1 = -2.0*c/a0, a2 = (1.0 - al)/a0;
        sCF.na1 = (float)(-a1); sCF.na2 = (float)(-a2); sCF.b0 = (float)b0;
        sCF.k1 = (float)(b1 - a1*b0); sCF.k2 = (float)(b2 - a2*b0);
        double m00 = -a1, m01 = 1.0, m10 = -a2, m11 = 0.0;
        for (int k = 0; k < 8; ++k) {          // A^256
            double t00 = m00*m00 + m01*m10, t01 = m00*m01 + m01*m11;
            double t10 = m10*m00 + m11*m10, t11 = m10*m01 + m11*m11;
            m00 = t00; m01 = t01; m10 = t10; m11 = t11;
        }
        for (int lv = 0; lv < BQ_LEV; ++lv) {
            sP[lv][0] = (float)m00; sP[lv][1] = (float)m01;
            sP[lv][2] = (float)m10; sP[lv][3] = (float)m11;
            double t00 = m00*m00 + m01*m10, t01 = m00*m01 + m01*m11;
            double t10 = m10*m00 + m11*m10, t11 = m10*m01 + m11*m11;
            m00 = t00; m01 = t01; m10 = t10; m11 = t11;
        }
    }
    __syncthreads();
    BQ cf = sCF;
    // thread samples [tid*256, +256) = 128 pairs; float2 idx = ((tid&3)*128 + j)*128 + tid>>2
    int base2 = (tid & 3) * 16384 + (tid >> 2);
    const float2* ip = in2 + base2;
    float2 ring[16];

#define BQ_LOAD(j0) { _Pragma("unroll") for (int j = 0; j < 16; ++j) ring[j] = __ldg(ip + (j0 + j)*LNC); }
#define BQ_BODY(STMT) \
    BQ_LOAD(0); \
    for (int bs = 0; bs < 112; bs += 16) { \
        _Pragma("unroll") for (int j = 0; j < 16; ++j) { \
            float2 xv = ring[j]; ring[j] = __ldg(ip + (bs + 16 + j)*LNC); \
            int jp = bs + j; (void)jp; STMT; } } \
    { int bs = 112; \
      _Pragma("unroll") for (int j = 0; j < 16; ++j) { \
            float2 xv = ring[j]; int jp = bs + j; (void)jp; STMT; } }

    // phase A1
    float z1 = 0.f, z2 = 0.f;
    BQ_BODY({ bqstep(xv.x, z1, z2, cf); bqstep(xv.y, z1, z2, cf); })
    float2 e1 = ks_scan(make_float2(z1, z2), sF, sP, tid);

    // phase B1+A2
    z1 = e1.x; z2 = e1.y;
    float w1 = 0.f, w2 = 0.f;
    BQ_BODY({ float y0 = bqstep_y(xv.x, z1, z2, cf); bqstep(y0, w1, w2, cf);
              float y1 = bqstep_y(xv.y, z1, z2, cf); bqstep(y1, w1, w2, cf); })
    float2 e2 = ks_scan(make_float2(w1, w2), sF, sP, tid);

    // phase B1+B2
    z1 = e1.x; z2 = e1.y; w1 = e2.x; w2 = e2.y;
    float2* op = out2 + base2;
    BQ_BODY({ float y0 = bqstep_y(xv.x, z1, z2, cf);
              float y1 = bqstep_y(xv.y, z1, z2, cf);
              float2 r; r.x = bqstep_y(y0, w1, w2, cf); r.y = bqstep_y(y1, w1, w2, cf);
              op[jp*LNC] = r; })
#undef BQ_BODY
#undef BQ_LOAD
}

// ---------------- band gain: elementwise float4 ----------------
struct GP { float ct, sc, et, se; };
__device__ __forceinline__ float comp_gain(float det, const GP& p)
{
    float xdb = 6.0205999132796239f * f_lg2(fmaxf(det, 1e-7f));
    float gdb = fminf(fminf(p.sc * (p.ct - xdb), p.se * (p.et - xdb)), 0.f);
    return f_ex2(gdb * DB2L);
}

__global__ void k_bandgain(const float* __restrict__ ct, const float* __restrict__ cr,
                           const float* __restrict__ et, const float* __restrict__ er)
{
    __shared__ GP sp[3];
    int b = blockIdx.y;
    int tid = threadIdx.x;
    if (tid < 3) {
        int idx = b*3 + tid;
        GP g; g.ct = ct[idx]; g.sc = 1.f - 1.f/cr[idx];
        g.et = et[idx]; g.se = 1.f - 1.f/er[idx];
        sp[tid] = g;
    }
    __syncthreads();
    int i = blockIdx.x * blockDim.x + tid;
    size_t p0 = (size_t)(b*2) * (T_LEN/4), p1 = p0 + T_LEN/4;
    float4 x0 = ((const float4*)g_xd)[p0 + i],  x1 = ((const float4*)g_xd)[p1 + i];
    float4 l0 = ((const float4*)g_low)[p0 + i], l1 = ((const float4*)g_low)[p1 + i];
    float4 h0 = ((const float4*)g_high)[p0 + i],h1 = ((const float4*)g_high)[p1 + i];
    float4 gl, gm, gh;
#define GL(L) { float ls = l0.L + l1.L, hs = h0.L + h1.L, xs = x0.L + x1.L; \
    gl.L = comp_gain(fabsf(ls), sp[0]); \
    gm.L = comp_gain(fabsf(xs - ls - hs), sp[1]); \
    gh.L = comp_gain(fabsf(hs), sp[2]); }
    GL(x) GL(y) GL(z) GL(w)
#undef GL
    ((float4*)g_gin)[(size_t)(0*NB + b)*(T_LEN/4) + i] = gl;
    ((float4*)g_gin)[(size_t)(1*NB + b)*(T_LEN/4) + i] = gm;
    ((float4*)g_gin)[(size_t)(2*NB + b)*(T_LEN/4) + i] = gh;
}

// ---------------- smoothing: paired (2-step composed), P-native ----------------
template<bool USEMIN, bool STORE, bool LIM>
__device__ __forceinline__ float sm_seg(const float2* __restrict__ sp, float2* __restrict__ dp,
                                        float f, float at, float rt,
                                        float A1, float A2, float AA11, float AAX, float AA22,
                                        float lt)
{
    float2 ring[16];
#pragma unroll
    for (int j = 0; j < 16; ++j) ring[j] = __ldg(sp + j*LNC);
#define SM_PAIR \
    { float g0 = gv.x, g1 = gv.y; \
      float t0 = at*g0, t1 = rt*g0, s0 = at*g1, s1 = rt*g1; \
      float u11 = fmaf(A1,t0,s0), u21 = fmaf(A2,t0,s1); \
      float u12 = fmaf(A1,t1,s0), u22 = fmaf(A2,t1,s1); \
      float P11 = fmaf(AA11,f,u11), P21 = fmaf(AAX,f,u21); \
      float P12 = fmaf(AAX,f,u12),  P22 = fmaf(AA22,f,u22); \
      float fn = USEMIN ? fminf(fminf(P11,P21),fminf(P12,P22)) \
                        : fmaxf(fmaxf(P11,P21),fmaxf(P12,P22)); \
      if (STORE) { \
          float q1 = fmaf(A1,f,t0), q2 = fmaf(A2,f,t1); \
          float f1 = USEMIN ? fminf(q1,q2) : fmaxf(q1,q2); \
          float2 o; \
          if (LIM) { o.x = fminf(1.f, __fdividef(lt, fmaxf(f1,1e-7f))); \
                     o.y = fminf(1.f, __fdividef(lt, fmaxf(fn,1e-7f))); } \
          else     { o.x = f1; o.y = fn; } \
          dp[jp*LNC] = o; } \
      f = fn; }
    for (int bs = 0; bs < QP-16; bs += 16) {
#pragma unroll
        for (int j = 0; j < 16; ++j) {
            float2 gv = ring[j]; ring[j] = __ldg(sp + (bs + 16 + j)*LNC);
            int jp = bs + j; (void)jp;
            SM_PAIR
        }
    }
    {
        int bs = QP-16;
#pragma unroll
        for (int j = 0; j < 16; ++j) {
            float2 gv = ring[j];
            int jp = bs + j; (void)jp;
            SM_PAIR
        }
    }
#undef SM_PAIR
    return f;
}

template<bool USEMIN, bool LIM>
__device__ __forceinline__ void sm_run(const float* __restrict__ src, float* __restrict__ dst,
                                       int c, float at, float rt, float lt, float initv)
{
    float A1 = 1.f - at, A2 = 1.f - rt;
    float AA11 = A1*A1, AAX = A1*A2, AA22 = A2*A2;
    const float2* s2 = (const float2*)src;
    float2* d2 = (float2*)dst;
    float f = initv;
    for (int seg = 0; seg < SM_W; ++seg) {
        int cc = c - SM_W + seg;
        if (cc >= 0)
            f = sm_seg<USEMIN, false, false>(s2 + cc, d2, f, at, rt, A1, A2, AA11, AAX, AA22, lt);
    }
    sm_seg<USEMIN, true, LIM>(s2 + c, d2 + c, f, at, rt, A1, A2, AA11, AAX, AA22, lt);
}

__global__ void k_smooth_band(const float* __restrict__ atms, const float* __restrict__ rtms)
{
    int seq = blockIdx.x, c = threadIdx.x;      // 48 x 128
    int band = seq >> 4, b = seq & 15;
    int idx = b*3 + band;
    float at = 1.f - __expf(-2200.f / (atms[idx] * 44100.f));
    float rt = 1.f - __expf(-2200.f / (rtms[idx] * 44100.f));
    const float* src = g_gin + (size_t)seq * T_LEN;
    float*       dst = g_gsm + (size_t)seq * T_LEN;
    if (at >= rt) sm_run<true,  false>(src, dst, c, at, rt, 0.f, 1.f);
    else          sm_run<false, false>(src, dst, c, at, rt, 0.f, 1.f);
}

__global__ void k_smooth_lim(const float* __restrict__ lth, const float* __restrict__ lat,
                             const float* __restrict__ lrt)
{
    int b = blockIdx.x, c = threadIdx.x;        // 16 x 128
    float at = 1.f - __expf(-2200.f / (lat[b] * 44100.f));
    float rt = 1.f - __expf(-2200.f / (lrt[b] * 44100.f));
    float lt = exp2f(lth[b] * DB2L);
    const float* src = g_det + (size_t)b * T_LEN;
    float*       dst = g_lg  + (size_t)b * T_LEN;
    if (at <= rt) sm_run<true,  true>(src, dst, c, at, rt, lt, 0.f);
    else          sm_run<false, true>(src, dst, c, at, rt, lt, 0.f);
}

// ---------------- mix + limiter detector: elementwise float4 ----------------
__global__ void k_mix(const float* __restrict__ mbmix)
{
    int b = blockIdx.y;
    float mb = __ldg(mbmix + b), om = 1.f - mb;
    int i = blockIdx.x * blockDim.x + threadIdx.x;
    size_t p0 = (size_t)(b*2) * (T_LEN/4), p1 = p0 + T_LEN/4;
    float4 x0 = ((const float4*)g_xd)[p0 + i],  x1 = ((const float4*)g_xd)[p1 + i];
    float4 l0 = ((const float4*)g_low)[p0 + i], l1 = ((const float4*)g_low)[p1 + i];
    float4 h0 = ((const float4*)g_high)[p0 + i],h1 = ((const float4*)g_high)[p1 + i];
    float4 gl = ((const float4*)g_gsm)[(size_t)(0*NB + b)*(T_LEN/4) + i];
    float4 gm = ((const float4*)g_gsm)[(size_t)(1*NB + b)*(T_LEN/4) + i];
    float4 gh = ((const float4*)g_gsm)[(size_t)(2*NB + b)*(T_LEN/4) + i];
    float4 m0, m1, dt;
#define ML(L) { \
    float mid0 = x0.L - l0.L - h0.L; \
    float y0 = l0.L*gl.L + mid0*gm.L + h0.L*gh.L; \
    float a0 = mb*y0 + om*x0.L; \
    float mid1 = x1.L - l1.L - h1.L; \
    float y1 = l1.L*gl.L + mid1*gm.L + h1.L*gh.L; \
    float a1 = mb*y1 + om*x1.L; \
    m0.L = a0; m1.L = a1; dt.L = fabsf(a0 + a1); }
    ML(x) ML(y) ML(z) ML(w)
#undef ML
    ((float4*)g_xm)[p0 + i] = m0;
    ((float4*)g_xm)[p1 + i] = m1;
    ((float4*)g_det)[(size_t)b*(T_LEN/4) + i] = dt;
}

// ---------------- final: P -> natural, apply limiter gain ----------------
__global__ void k_final(float* __restrict__ out)
{
    __shared__ float2 sA[32][33], sB[32][33];
    int b = blockIdx.y;
    int bx = blockIdx.x;
    int c0 = (bx >> 4) * 32, q0 = (bx & 15) * 32;
    int tx = threadIdx.x, ty = threadIdx.y;
    size_t A = (size_t)(q0 + ty) * LNC + c0 + tx;           // P, coalesced in tx
    const float2* lg2v = (const float2*)g_lg + (size_t)b * P2;
    const float2* xm2  = (const float2*)g_xm;
    float2 g  = __ldg(lg2v + A);
    float2 m0 = __ldg(xm2 + (size_t)(b*2)   * P2 + A);
    float2 m1 = __ldg(xm2 + (size_t)(b*2+1) * P2 + A);
    m0.x *= g.x; m0.y *= g.y;
    m1.x *= g.x; m1.y *= g.y;
    sA[tx][ty] = m0;
    sB[tx][ty] = m1;
    __syncthreads();
    float2* o0 = (float2*)out + (size_t)(b*2) * P2;
    float2* o1 = o0 + P2;
    size_t N = (size_t)(c0 + ty) * QP + q0 + tx;            // natural, coalesced in tx
    o0[N] = sA[ty][tx];
    o1[N] = sB[ty][tx];
}

// ---------------- launcher ----------------
extern "C" void kernel_launch(void* const* d_in, const int* in_sizes, int n_in,
                              void* d_out, int out_size)
{
    const float* x     = (const float*)d_in[0];
    const float* drive = (const float*)d_in[1];
    const float* dmix  = (const float*)d_in[2];
    const float* locut = (const float*)d_in[3];
    const float* hicut = (const float*)d_in[4];
    const float* mbmix = (const float*)d_in[5];
    const float* ct    = (const float*)d_in[6];
    const float* cr    = (const float*)d_in[7];
    const float* et    = (const float*)d_in[8];
    const float* er    = (const float*)d_in[9];
    const float* atms  = (const float*)d_in[10];
    const float* rtms  = (const float*)d_in[11];
    const float* lth   = (const float*)d_in[12];
    const float* lat   = (const float*)d_in[13];
    const float* lrt   = (const float*)d_in[14];
    (void)in_sizes; (void)n_in; (void)out_size;

    dim3 tile(32, 32);
    k_dist<<<dim3(64, NSEQ), tile>>>(x, drive, dmix);
    k_bq<<<64, BQ_NT>>>(locut, hicut);
    k_bandgain<<<dim3(128, NB), 256>>>(ct, cr, et, er);
    k_smooth_band<<<NBS, LNC>>>(atms, rtms);
    k_mix<<<dim3(128, NB), 256>>>(mbmix);
    k_smooth_lim<<<NB, LNC>>>(lth, lat, lrt);
    k_final<<<dim3(64, NB), tile>>>((float*)d_out);
}

// round 9
// speedup vs baseline: 7.6356x; 1.1868x over previous
#include <cuda_runtime.h>
#include <math.h>

#define T_LEN 131072
#define NB 16
#define NCHA 2
#define NSEQ (NB*NCHA)
#define NBS 48
#define DB2L 0.16609640474436813f   // log2(10)/20

// Q layout per plane: t -> chunk c = t>>10 (128 of them), quad q4 = (t&1023)>>2 (256), lane t&3
//   float4 index = q4*128 + c
#define LNC 128
#define Q4  256
#define P4  32768          // float4 per plane

#define BQ_NT 512          // biquad: 512 threads x 256-sample chunks
#define BQ_LEV 9
#define SM_W 16            // smoother warmup chunks (16384 samples)

__device__ float g_xd  [NSEQ*T_LEN];
__device__ float g_low [NSEQ*T_LEN];
__device__ float g_high[NSEQ*T_LEN];
__device__ float g_gin [NBS*T_LEN];
__device__ float g_gsm [NBS*T_LEN];
__device__ float g_xm  [NSEQ*T_LEN];
__device__ float g_det [NB*T_LEN];
__device__ float g_lg  [NB*T_LEN];

struct BQ { float na1, na2, b0, k1, k2; };

__device__ __forceinline__ float f_lg2(float x){ float r; asm("lg2.approx.f32 %0,%1;":"=f"(r):"f"(x)); return r; }
__device__ __forceinline__ float f_ex2(float x){ float r; asm("ex2.approx.f32 %0,%1;":"=f"(r):"f"(x)); return r; }

// ---------------- dist: natural -> Q, tanh drive mix ----------------
__global__ void k_dist(const float* __restrict__ x, const float* __restrict__ drive,
                       const float* __restrict__ dmix)
{
    __shared__ float4 sT[32][33];
    __shared__ float sw, sgd;
    int s = blockIdx.y, b = s >> 1;
    int bx = blockIdx.x;
    int c0 = (bx >> 3) * 32, q0 = (bx & 7) * 32;
    int tx = threadIdx.x, ty = threadIdx.y;
    if (tx == 0 && ty == 0) { sw = dmix[b]; sgd = exp2f(drive[b] * DB2L); }
    __syncthreads();
    float w = sw, gd = sgd, ow = 1.f - w;
    const float4* xin = (const float4*)x + (size_t)s * P4;
    float4 v = __ldg(xin + (c0 + ty) * Q4 + q0 + tx);        // natural: c over ty, q4 over tx
#define TL(L) { \
    float z = fminf(fmaxf(v.L * gd, -15.f), 15.f); \
    float e = __expf(2.f * z); \
    float th = __fdividef(e - 1.f, e + 1.f); \
    v.L = fmaf(w, th, ow * v.L); }
    TL(x) TL(y) TL(z) TL(w)
#undef TL
    sT[ty][tx] = v;
    __syncthreads();
    float4* xo = (float4*)g_xd + (size_t)s * P4;
    xo[(q0 + ty) * LNC + c0 + tx] = sT[tx][ty];              // Q: q4 over ty, c over tx
}

// ---------------- fused LR4 biquad ----------------
__device__ __forceinline__ void bqstep(float x, float& z1, float& z2, const BQ& c)
{
    float t  = fmaf(c.k1, x, z2);
    float n2 = fmaf(c.na2, z1, c.k2 * x);
    z1 = fmaf(c.na1, z1, t);
    z2 = n2;
}
__device__ __forceinline__ float bqstep_y(float x, float& z1, float& z2, const BQ& c)
{
    float y  = fmaf(c.b0, x, z1);
    float t  = fmaf(c.k1, x, z2);
    float n2 = fmaf(c.na2, z1, c.k2 * x);
    z1 = fmaf(c.na1, z1, t);
    z2 = n2;
    return y;
}

__device__ __forceinline__ float2 ks_scan(float2 my, float2* sF, float (*sP)[4], int tid)
{
    __syncthreads();
#pragma unroll
    for (int lv = 0; lv < BQ_LEV; ++lv) {
        sF[tid] = my;
        __syncthreads();
        int d = 1 << lv;
        if (tid >= d) {
            float2 o = sF[tid - d];
            my.x += sP[lv][0]*o.x + sP[lv][1]*o.y;
            my.y += sP[lv][2]*o.x + sP[lv][3]*o.y;
        }
        __syncthreads();
    }
    sF[tid] = my;
    __syncthreads();
    float2 e = (tid > 0) ? sF[tid-1] : make_float2(0.f, 0.f);
    __syncthreads();
    return e;
}

__global__ void k_bq(const float* __restrict__ locut, const float* __restrict__ hicut)
{
    __shared__ float2 sF[BQ_NT];
    __shared__ float  sP[BQ_LEV][4];
    __shared__ BQ     sCF;
    int blk = blockIdx.x;
    int f = blk >> 5, s = blk & 31, b = s >> 1;
    const float4* in4 = (const float4*)g_xd + (size_t)s * P4;
    float4* out4 = (float4*)(f ? g_high : g_low) + (size_t)s * P4;
    int tid = threadIdx.x;

    if (tid == 0) {
        double cut = f ? (double)hicut[b] : (double)locut[b];
        double w0 = 2.0 * 3.14159265358979323846 * cut / 44100.0;
        double al = sin(w0) * 0.70710678118654752;
        double c  = cos(w0);
        double b0, b1, b2;
        if (f == 0) { b0 = (1.0 - c)*0.5; b1 = 1.0 - c;    b2 = (1.0 - c)*0.5; }
        else        { b0 = (1.0 + c)*0.5; b1 = -(1.0 + c); b2 = (1.0 + c)*0.5; }
        double a0 = 1.0 + al;
        b0 /= a0; b1 /= a0; b2 /= a0;
        double a1 = -2.0*c/a0, a2 = (1.0 - al)/a0;
        sCF.na1 = (float)(-a1); sCF.na2 = (float)(-a2); sCF.b0 = (float)b0;
        sCF.k1 = (float)(b1 - a1*b0); sCF.k2 = (float)(b2 - a2*b0);
        double m00 = -a1, m01 = 1.0, m10 = -a2, m11 = 0.0;
        for (int k = 0; k < 8; ++k) {          // A^256
            double t00 = m00*m00 + m01*m10, t01 = m00*m01 + m01*m11;
            double t10 = m10*m00 + m11*m10, t11 = m10*m01 + m11*m11;
            m00 = t00; m01 = t01; m10 = t10; m11 = t11;
        }
        for (int lv = 0; lv < BQ_LEV; ++lv) {
            sP[lv][0] = (float)m00; sP[lv][1] = (float)m01;
            sP[lv][2] = (float)m10; sP[lv][3] = (float)m11;
            double t00 = m00*m00 + m01*m10, t01 = m00*m01 + m01*m11;
            double t10 = m10*m00 + m11*m10, t11 = m10*m01 + m11*m11;
            m00 = t00; m01 = t01; m10 = t10; m11 = t11;
        }
    }
    __syncthreads();
    BQ cf = sCF;
    // thread samples [tid*256, +256) = 64 float4; idx = ((tid&3)*64 + j)*128 + tid>>2
    const float4* ip = in4 + (tid & 3) * 64 * LNC + (tid >> 2);
    float4 ring[8];

#define BQ_BODY(STMT) \
    { _Pragma("unroll") for (int j = 0; j < 8; ++j) ring[j] = __ldg(ip + j*LNC); } \
    for (int bs = 0; bs < 56; bs += 8) { \
        _Pragma("unroll") for (int j = 0; j < 8; ++j) { \
            float4 xv = ring[j]; ring[j] = __ldg(ip + (bs + 8 + j)*LNC); \
            int jp = bs + j; (void)jp; STMT; } } \
    { int bs = 56; \
      _Pragma("unroll") for (int j = 0; j < 8; ++j) { \
            float4 xv = ring[j]; int jp = bs + j; (void)jp; STMT; } }

    // phase A1: stage-1 zero-state
    float z1 = 0.f, z2 = 0.f;
    BQ_BODY({ bqstep(xv.x, z1, z2, cf); bqstep(xv.y, z1, z2, cf);
              bqstep(xv.z, z1, z2, cf); bqstep(xv.w, z1, z2, cf); })
    float2 e1 = ks_scan(make_float2(z1, z2), sF, sP, tid);

    // phase B1+A2
    z1 = e1.x; z2 = e1.y;
    float w1 = 0.f, w2 = 0.f;
    BQ_BODY({ bqstep(bqstep_y(xv.x, z1, z2, cf), w1, w2, cf);
              bqstep(bqstep_y(xv.y, z1, z2, cf), w1, w2, cf);
              bqstep(bqstep_y(xv.z, z1, z2, cf), w1, w2, cf);
              bqstep(bqstep_y(xv.w, z1, z2, cf), w1, w2, cf); })
    float2 e2 = ks_scan(make_float2(w1, w2), sF, sP, tid);

    // phase B1+B2: emit
    z1 = e1.x; z2 = e1.y; w1 = e2.x; w2 = e2.y;
    float4* op = out4 + (tid & 3) * 64 * LNC + (tid >> 2);
    BQ_BODY({ float4 r;
              r.x = bqstep_y(bqstep_y(xv.x, z1, z2, cf), w1, w2, cf);
              r.y = bqstep_y(bqstep_y(xv.y, z1, z2, cf), w1, w2, cf);
              r.z = bqstep_y(bqstep_y(xv.z, z1, z2, cf), w1, w2, cf);
              r.w = bqstep_y(bqstep_y(xv.w, z1, z2, cf), w1, w2, cf);
              op[jp*LNC] = r; })
#undef BQ_BODY
}

// ---------------- band gain: elementwise float4 ----------------
struct GP { float ct, sc, et, se; };
__device__ __forceinline__ float comp_gain(float det, const GP& p)
{
    float xdb = 6.0205999132796239f * f_lg2(fmaxf(det, 1e-7f));
    float gdb = fminf(fminf(p.sc * (p.ct - xdb), p.se * (p.et - xdb)), 0.f);
    return f_ex2(gdb * DB2L);
}

__global__ void k_bandgain(const float* __restrict__ ct, const float* __restrict__ cr,
                           const float* __restrict__ et, const float* __restrict__ er)
{
    __shared__ GP sp[3];
    int b = blockIdx.y;
    int tid = threadIdx.x;
    if (tid < 3) {
        int idx = b*3 + tid;
        GP g; g.ct = ct[idx]; g.sc = 1.f - 1.f/cr[idx];
        g.et = et[idx]; g.se = 1.f - 1.f/er[idx];
        sp[tid] = g;
    }
    __syncthreads();
    int i = blockIdx.x * blockDim.x + tid;
    size_t p0 = (size_t)(b*2) * P4, p1 = p0 + P4;
    float4 x0 = ((const float4*)g_xd)[p0 + i],  x1 = ((const float4*)g_xd)[p1 + i];
    float4 l0 = ((const float4*)g_low)[p0 + i], l1 = ((const float4*)g_low)[p1 + i];
    float4 h0 = ((const float4*)g_high)[p0 + i],h1 = ((const float4*)g_high)[p1 + i];
    float4 gl, gm, gh;
#define GL(L) { float ls = l0.L + l1.L, hs = h0.L + h1.L, xs = x0.L + x1.L; \
    gl.L = comp_gain(fabsf(ls), sp[0]); \
    gm.L = comp_gain(fabsf(xs - ls - hs), sp[1]); \
    gh.L = comp_gain(fabsf(hs), sp[2]); }
    GL(x) GL(y) GL(z) GL(w)
#undef GL
    ((float4*)g_gin)[(size_t)(0*NB + b)*P4 + i] = gl;
    ((float4*)g_gin)[(size_t)(1*NB + b)*P4 + i] = gm;
    ((float4*)g_gin)[(size_t)(2*NB + b)*P4 + i] = gh;
}

// ---------------- smoothing: 2-step composed, Q-native float4 ----------------
template<bool USEMIN, bool F1>
__device__ __forceinline__ float pair_step(float f, float g0, float g1, float* f1out,
    float at, float rt, float A1, float A2, float AA11, float AAX, float AA22)
{
    float t0 = at*g0, t1 = rt*g0, s0 = at*g1, s1 = rt*g1;
    float u11 = fmaf(A1,t0,s0);
    float u21 = fmaf(A2,t0,s1);
    float u12 = fmaf(A1,t1,s0);
    float u22 = fmaf(A2,t1,s1);
    float um  = USEMIN ? fminf(u21,u12) : fmaxf(u21,u12);   // same slope AAX -> fold off-chain
    float P11 = fmaf(AA11,f,u11);
    float Pm  = fmaf(AAX ,f,um );
    float P22 = fmaf(AA22,f,u22);
    if (F1) {
        float q1 = fmaf(A1,f,t0), q2 = fmaf(A2,f,t1);
        *f1out = USEMIN ? fminf(q1,q2) : fmaxf(q1,q2);
    }
    return USEMIN ? fminf(P11,fminf(Pm,P22)) : fmaxf(P11,fmaxf(Pm,P22));
}

template<bool USEMIN, bool STORE, bool LIM>
__device__ __forceinline__ float sm_seg(const float4* __restrict__ sp, float4* __restrict__ dp,
    float f, float at, float rt, float A1, float A2,
    float AA11, float AAX, float AA22, float lt)
{
    float4 ring[16];
#pragma unroll
    for (int j = 0; j < 16; ++j) ring[j] = __ldg(sp + j*LNC);
#define SM_Q { \
    float f1a = 0.f, f1b = 0.f; \
    f = pair_step<USEMIN,STORE>(f, gv.x, gv.y, &f1a, at,rt,A1,A2,AA11,AAX,AA22); \
    float fA = f; \
    f = pair_step<USEMIN,STORE>(f, gv.z, gv.w, &f1b, at,rt,A1,A2,AA11,AAX,AA22); \
    if (STORE) { \
        float4 o; o.x = f1a; o.y = fA; o.z = f1b; o.w = f; \
        if (LIM) { \
            o.x = fminf(1.f, __fdividef(lt, fmaxf(o.x, 1e-7f))); \
            o.y = fminf(1.f, __fdividef(lt, fmaxf(o.y, 1e-7f))); \
            o.z = fminf(1.f, __fdividef(lt, fmaxf(o.z, 1e-7f))); \
            o.w = fminf(1.f, __fdividef(lt, fmaxf(o.w, 1e-7f))); } \
        dp[jp*LNC] = o; } }
    for (int bs = 0; bs < Q4-16; bs += 16) {
#pragma unroll
        for (int j = 0; j < 16; ++j) {
            float4 gv = ring[j]; ring[j] = __ldg(sp + (bs + 16 + j)*LNC);
            int jp = bs + j; (void)jp;
            SM_Q
        }
    }
    { int bs = Q4-16;
#pragma unroll
      for (int j = 0; j < 16; ++j) {
          float4 gv = ring[j];
          int jp = bs + j; (void)jp;
          SM_Q
      } }
#undef SM_Q
    return f;
}

template<bool USEMIN, bool LIM>
__device__ __forceinline__ void sm_run(const float* __restrict__ src, float* __restrict__ dst,
                                       int c, float at, float rt, float lt, float initv)
{
    float A1 = 1.f - at, A2 = 1.f - rt;
    float AA11 = A1*A1, AAX = A1*A2, AA22 = A2*A2;
    const float4* s4 = (const float4*)src;
    float4* d4 = (float4*)dst;
    float f = initv;
    for (int seg = 0; seg < SM_W; ++seg) {
        int cc = c - SM_W + seg;
        if (cc >= 0)
            f = sm_seg<USEMIN, false, false>(s4 + cc, d4, f, at, rt, A1, A2, AA11, AAX, AA22, lt);
    }
    sm_seg<USEMIN, true, LIM>(s4 + c, d4 + c, f, at, rt, A1, A2, AA11, AAX, AA22, lt);
}

__global__ void k_smooth_band(const float* __restrict__ atms, const float* __restrict__ rtms)
{
    int seq = blockIdx.x, c = threadIdx.x;      // 48 x 128
    int band = seq >> 4, b = seq & 15;
    int idx = b*3 + band;
    float at = 1.f - __expf(-2200.f / (atms[idx] * 44100.f));
    float rt = 1.f - __expf(-2200.f / (rtms[idx] * 44100.f));
    const float* src = g_gin + (size_t)seq * T_LEN;
    float*       dst = g_gsm + (size_t)seq * T_LEN;
    if (at >= rt) sm_run<true,  false>(src, dst, c, at, rt, 0.f, 1.f);
    else          sm_run<false, false>(src, dst, c, at, rt, 0.f, 1.f);
}

__global__ void k_smooth_lim(const float* __restrict__ lth, const float* __restrict__ lat,
                             const float* __restrict__ lrt)
{
    int b = blockIdx.x, c = threadIdx.x;        // 16 x 128
    float at = 1.f - __expf(-2200.f / (lat[b] * 44100.f));
    float rt = 1.f - __expf(-2200.f / (lrt[b] * 44100.f));
    float lt = exp2f(lth[b] * DB2L);
    const float* src = g_det + (size_t)b * T_LEN;
    float*       dst = g_lg  + (size_t)b * T_LEN;
    if (at <= rt) sm_run<true,  true>(src, dst, c, at, rt, lt, 0.f);
    else          sm_run<false, true>(src, dst, c, at, rt, lt, 0.f);
}

// ---------------- mix + limiter detector: elementwise float4 ----------------
__global__ void k_mix(const float* __restrict__ mbmix)
{
    int b = blockIdx.y;
    float mb = __ldg(mbmix + b), om = 1.f - mb;
    int i = blockIdx.x * blockDim.x + threadIdx.x;
    size_t p0 = (size_t)(b*2) * P4, p1 = p0 + P4;
    float4 x0 = ((const float4*)g_xd)[p0 + i],  x1 = ((const float4*)g_xd)[p1 + i];
    float4 l0 = ((const float4*)g_low)[p0 + i], l1 = ((const float4*)g_low)[p1 + i];
    float4 h0 = ((const float4*)g_high)[p0 + i],h1 = ((const float4*)g_high)[p1 + i];
    float4 gl = ((const float4*)g_gsm)[(size_t)(0*NB + b)*P4 + i];
    float4 gm = ((const float4*)g_gsm)[(size_t)(1*NB + b)*P4 + i];
    float4 gh = ((const float4*)g_gsm)[(size_t)(2*NB + b)*P4 + i];
    float4 m0, m1, dt;
#define ML(L) { \
    float mid0 = x0.L - l0.L - h0.L; \
    float y0 = l0.L*gl.L + mid0*gm.L + h0.L*gh.L; \
    float a0 = mb*y0 + om*x0.L; \
    float mid1 = x1.L - l1.L - h1.L; \
    float y1 = l1.L*gl.L + mid1*gm.L + h1.L*gh.L; \
    float a1 = mb*y1 + om*x1.L; \
    m0.L = a0; m1.L = a1; dt.L = fabsf(a0 + a1); }
    ML(x) ML(y) ML(z) ML(w)
#undef ML
    ((float4*)g_xm)[p0 + i] = m0;
    ((float4*)g_xm)[p1 + i] = m1;
    ((float4*)g_det)[(size_t)b*P4 + i] = dt;
}

// ---------------- final: Q -> natural, apply limiter gain ----------------
__global__ void k_final(float* __restrict__ out)
{
    __shared__ float4 sA[32][33], sB[32][33];
    int b = blockIdx.y;
    int bx = blockIdx.x;
    int c0 = (bx >> 3) * 32, q0 = (bx & 7) * 32;
    int tx = threadIdx.x, ty = threadIdx.y;
    size_t A = (size_t)(q0 + ty) * LNC + c0 + tx;            // Q, coalesced in tx
    const float4* lg4 = (const float4*)g_lg + (size_t)b * P4;
    const float4* xm4 = (const float4*)g_xm;
    float4 g  = __ldg(lg4 + A);
    float4 m0 = __ldg(xm4 + (size_t)(b*2)   * P4 + A);
    float4 m1 = __ldg(xm4 + (size_t)(b*2+1) * P4 + A);
    m0.x *= g.x; m0.y *= g.y; m0.z *= g.z; m0.w *= g.w;
    m1.x *= g.x; m1.y *= g.y; m1.z *= g.z; m1.w *= g.w;
    sA[tx][ty] = m0;
    sB[tx][ty] = m1;
    __syncthreads();
    float4* o0 = (float4*)out + (size_t)(b*2) * P4;
    float4* o1 = o0 + P4;
    size_t N = (size_t)(c0 + ty) * Q4 + q0 + tx;             // natural, coalesced in tx
    o0[N] = sA[ty][tx];
    o1[N] = sB[ty][tx];
}

// ---------------- launcher ----------------
extern "C" void kernel_launch(void* const* d_in, const int* in_sizes, int n_in,
                              void* d_out, int out_size)
{
    const float* x     = (const float*)d_in[0];
    const float* drive = (const float*)d_in[1];
    const float* dmix  = (const float*)d_in[2];
    const float* locut = (const float*)d_in[3];
    const float* hicut = (const float*)d_in[4];
    const float* mbmix = (const float*)d_in[5];
    const float* ct    = (const float*)d_in[6];
    const float* cr    = (const float*)d_in[7];
    const float* et    = (const float*)d_in[8];
    const float* er    = (const float*)d_in[9];
    const float* atms  = (const float*)d_in[10];
    const float* rtms  = (const float*)d_in[11];
    const float* lth   = (const float*)d_in[12];
    const float* lat   = (const float*)d_in[13];
    const float* lrt   = (const float*)d_in[14];
    (void)in_sizes; (void)n_in; (void)out_size;

    dim3 tile(32, 32);
    k_dist<<<dim3(32, NSEQ), tile>>>(x, drive, dmix);
    k_bq<<<64, BQ_NT>>>(locut, hicut);
    k_bandgain<<<dim3(128, NB), 256>>>(ct, cr, et, er);
    k_smooth_band<<<NBS, LNC>>>(atms, rtms);
    k_mix<<<dim3(128, NB), 256>>>(mbmix);
    k_smooth_lim<<<NB, LNC>>>(lth, lat, lrt);
    k_final<<<dim3(32, NB), tile>>>((float*)d_out);
}